// round 13
// baseline (speedup 1.0000x reference)
#include <cuda_runtime.h>
#include <cuda_bf16.h>
#include <mma.h>
#include <cstdint>
#include <math.h>

using namespace nvcuda;

// ---------------- problem constants ----------------
#define Bn   32
#define Sn   16
#define Ln   64
#define En   300
#define Pn   100
#define Hn   256
#define Gn   1024
#define DATT 612
#define N1   (Bn*Sn)
#define M1   (N1*Ln)
#define DIN1 (En+Pn)
#define NBATT 5             // 640/128
#define XKP  416            // padded K for x (400)
#define ZKP  640            // padded K/N for 612

typedef unsigned long long u64;
typedef __nv_bfloat16 bf16;

// ---------------- scratch (device globals) ----------------------------------
__device__ float d_gpre[2*M1*Gn];
__device__ float d_z[M1*DATT];
__device__ float d_scp[M1*NBATT];
__device__ float d_scores[M1];
__device__ float d_senvec[N1*2*Hn];
__device__ float d_gpre2[2*N1*Gn];
__device__ float d_z2[N1*DATT];
__device__ float d_hT[2*Bn*Hn];
__device__ float d_scp2[N1*NBATT];
__device__ float d_scores2[N1];
__device__ float d_docvec[Bn*2*Hn];
__device__ float d_wtf[Hn*Gn];
__device__ float d_wtb[Hn*Gn];
__device__ float d_stf[Hn*Gn];
__device__ float d_stb[Hn*Gn];
__device__ float d_brep[16*Gn];     // replicated bias (16 identical rows)
__device__ bf16 g_xhi[M1*XKP];
__device__ bf16 g_xlo[M1*XKP];
__device__ bf16 g_zhi[(size_t)M1*ZKP];
__device__ bf16 g_zlo[(size_t)M1*ZKP];
__device__ bf16 g_sxhi[N1*ZKP];
__device__ bf16 g_sxlo[N1*ZKP];
__device__ bf16 g_z2hi[N1*ZKP];
__device__ bf16 g_z2lo[N1*ZKP];
__device__ bf16 g_wihf_hi[Gn*XKP];
__device__ bf16 g_wihf_lo[Gn*XKP];
__device__ bf16 g_wihb_hi[Gn*XKP];
__device__ bf16 g_wihb_lo[Gn*XKP];
__device__ bf16 g_sihf_hi[Gn*ZKP];
__device__ bf16 g_sihf_lo[Gn*ZKP];
__device__ bf16 g_sihb_hi[Gn*ZKP];
__device__ bf16 g_sihb_lo[Gn*ZKP];
__device__ bf16 g_wWt_hi[ZKP*ZKP];
__device__ bf16 g_wWt_lo[ZKP*ZKP];
__device__ bf16 g_sWt_hi[ZKP*ZKP];
__device__ bf16 g_sWt_lo[ZKP*ZKP];

__device__ __forceinline__ float sigmoidf(float x) { return 1.0f / (1.0f + expf(-x)); }

__device__ __forceinline__ void fma2(u64& d, u64 a, u64 b) {
    asm("fma.rn.f32x2 %0, %1, %2, %3;" : "=l"(d) : "l"(a), "l"(b), "l"(d));
}
__device__ __forceinline__ u64 pack2(float x, float y) {
    u64 r; asm("mov.b64 %0, {%1,%2};" : "=l"(r) : "f"(x), "f"(y)); return r;
}
__device__ __forceinline__ void unpack2(float& lo, float& hi, u64 v) {
    asm("mov.b64 {%0,%1}, %2;" : "=f"(lo), "=f"(hi) : "l"(v));
}
__device__ __forceinline__ void split_bf16(float v, bf16& h, bf16& l) {
    h = __float2bfloat16(v);
    l = __float2bfloat16(v - __bfloat162float(h));
}
__device__ __forceinline__ uint32_t smem_u32(const void* p) {
    return (uint32_t)__cvta_generic_to_shared(p);
}
__device__ __forceinline__ void cp16(uint32_t dst, const void* src) {
    asm volatile("cp.async.cg.shared.global [%0], [%1], 16;" :: "r"(dst), "l"(src));
}
#define CP_COMMIT() asm volatile("cp.async.commit_group;" ::: "memory")
#define CP_WAIT0()  asm volatile("cp.async.wait_group 0;" ::: "memory")

// ======================= WMMA split-bf16 GEMM, 256x128 CTA tile ==============
// C[M,Nc] = A[M,KP] @ B[*,KP]^T, pre-split bf16 hi/lo, KP mult of 32,
// M mult 256, Nc mult 128. Warp tile 64x64 (acc[4][4]); 2-stage cp.async,
// K-step 32; tiles padded to 40-elem rows (conflict-free LDSM).
// attn==0: accumulators init from d_brep (bias) -> direct global store.
// attn!=0: per-warp smem tile (ldm 20, mult of 4) + tanh/proj reduction ->
//          C[m*gridDim.x + bx] = sum_{n<Nv} tanh(acc+bias[n])*proj[n]
// smem: 2 stages x (Ahi 256x40 | Alo | Bhi 128x40 | Blo) = 122880B;
// red[256] at +122880; wbuf 8 x 16x20 f32 at +123904. Total 134144B.
#define STB   61440           // stage stride, bytes
#define STE   30720           // stage stride, elems
#define GEMM_SMEM2 134144

__global__ __launch_bounds__(256, 1)
void gemm_wb(const bf16* __restrict__ Ahi, const bf16* __restrict__ Alo,
             const bf16* __restrict__ Bhi, const bf16* __restrict__ Blo,
             const float* __restrict__ brep, const float* __restrict__ bias,
             const float* __restrict__ proj,
             float* __restrict__ C, int M, int Nc, int KP, int Nv, int attn)
{
    extern __shared__ float dynsm[];
    bf16* sb    = (bf16*)dynsm;        // staged tiles
    float* red  = dynsm + 30720;       // byte 122880, 256 floats
    float* wbuf = dynsm + 30976;       // 8 warps x 320 floats (16x20)

    const int tid = threadIdx.x;
    const int m0 = blockIdx.y * 256;
    const int n0 = blockIdx.x * 128;
    const int w  = tid >> 5;
    const int lane = tid & 31;
    const int wm = w >> 1;             // 0..3 (64-row band)
    const int wn = w & 1;              // 0..1 (64-col band)

    wmma::fragment<wmma::accumulator, 16, 16, 16, float> acc[4][4];
    if (attn == 0) {
#pragma unroll
        for (int i = 0; i < 4; i++)
#pragma unroll
            for (int j = 0; j < 4; j++)
                wmma::load_matrix_sync(acc[i][j], brep + n0 + wn*64 + j*16, Gn,
                                       wmma::mem_row_major);
    } else {
#pragma unroll
        for (int i = 0; i < 4; i++)
#pragma unroll
            for (int j = 0; j < 4; j++)
                wmma::fill_fragment(acc[i][j], 0.0f);
    }

    const int nk   = KP / 32;
    const uint32_t sbase = smem_u32(sb);
    const uint32_t boffA = (uint32_t)(tid * 80);
    const int rowB = tid & 127;
    const int half = tid >> 7;
    const uint32_t boffB = (uint32_t)(rowB * 80 + half * 32);

    const bf16* __restrict__ pah = Ahi + (size_t)(m0 + tid) * KP;
    const bf16* __restrict__ pal = Alo + (size_t)(m0 + tid) * KP;
    const bf16* __restrict__ pbh = Bhi + (size_t)(n0 + rowB) * KP + half * 16;
    const bf16* __restrict__ pbl = Blo + (size_t)(n0 + rowB) * KP + half * 16;

    // stage chunk 0 into buffer 0
    {
        const uint32_t dA = sbase + boffA;
        const uint32_t dB = sbase + 40960 + boffB;
        cp16(dA +  0, pah);      cp16(dA + 16, pah +  8);
        cp16(dA + 32, pah + 16); cp16(dA + 48, pah + 24);
        cp16(dA + 20480 +  0, pal);      cp16(dA + 20480 + 16, pal +  8);
        cp16(dA + 20480 + 32, pal + 16); cp16(dA + 20480 + 48, pal + 24);
        cp16(dB +  0, pbh);      cp16(dB + 16, pbh + 8);
        cp16(dB + 10240 + 0, pbl); cp16(dB + 10240 + 16, pbl + 8);
        CP_COMMIT();
        CP_WAIT0();
    }
    __syncthreads();

    for (int kc = 0; kc < nk; kc++) {
        const int cur = kc & 1;
        if (kc + 1 < nk) {
            const int go = (kc + 1) * 32;
            const uint32_t dA = sbase + (uint32_t)((cur ^ 1) * STB) + boffA;
            const uint32_t dB = sbase + (uint32_t)((cur ^ 1) * STB) + 40960 + boffB;
            cp16(dA +  0, pah + go);      cp16(dA + 16, pah + go +  8);
            cp16(dA + 32, pah + go + 16); cp16(dA + 48, pah + go + 24);
            cp16(dA + 20480 +  0, pal + go);      cp16(dA + 20480 + 16, pal + go +  8);
            cp16(dA + 20480 + 32, pal + go + 16); cp16(dA + 20480 + 48, pal + go + 24);
            cp16(dB +  0, pbh + go);      cp16(dB + 16, pbh + go + 8);
            cp16(dB + 10240 + 0, pbl + go); cp16(dB + 10240 + 16, pbl + go + 8);
            CP_COMMIT();
        }
        const bf16* Ah = sb + cur * STE;
        const bf16* Al = Ah + 10240;
        const bf16* Bh = Ah + 20480;
        const bf16* Bl = Ah + 25600;
#pragma unroll
        for (int kf = 0; kf < 2; kf++) {
            wmma::fragment<wmma::matrix_a, 16, 16, 16, bf16, wmma::row_major> ah[4], al[4];
#pragma unroll
            for (int i = 0; i < 4; i++) {
                wmma::load_matrix_sync(ah[i], Ah + (wm*64 + i*16)*40 + kf*16, 40);
                wmma::load_matrix_sync(al[i], Al + (wm*64 + i*16)*40 + kf*16, 40);
            }
#pragma unroll
            for (int j = 0; j < 4; j++) {
                wmma::fragment<wmma::matrix_b, 16, 16, 16, bf16, wmma::col_major> bh, bl;
                wmma::load_matrix_sync(bh, Bh + (wn*64 + j*16)*40 + kf*16, 40);
                wmma::load_matrix_sync(bl, Bl + (wn*64 + j*16)*40 + kf*16, 40);
#pragma unroll
                for (int i = 0; i < 4; i++) {
                    wmma::mma_sync(acc[i][j], ah[i], bh, acc[i][j]);
                    wmma::mma_sync(acc[i][j], ah[i], bl, acc[i][j]);
                    wmma::mma_sync(acc[i][j], al[i], bh, acc[i][j]);
                }
            }
        }
        if (kc + 1 < nk) CP_WAIT0();
        __syncthreads();
    }

    if (attn == 0) {
        // direct global store (bias already in accumulators)
#pragma unroll
        for (int i = 0; i < 4; i++)
#pragma unroll
            for (int j = 0; j < 4; j++)
                wmma::store_matrix_sync(
                    C + (size_t)(m0 + wm*64 + i*16) * Nc + n0 + wn*64 + j*16,
                    acc[i][j], Nc, wmma::mem_row_major);
    } else {
        // per-warp tanh/proj reduction via 16x20 smem tile (ldm mult of 4)
        red[tid] = 0.f;
        __syncthreads();
        float* wb = wbuf + w * 320;
#pragma unroll
        for (int i = 0; i < 4; i++) {
#pragma unroll
            for (int j = 0; j < 4; j++) {
                wmma::store_matrix_sync(wb, acc[i][j], 20, wmma::mem_row_major);
                __syncwarp();
                if (lane < 16) {
                    const int nb = n0 + wn*64 + j*16;
                    float part = 0.f;
#pragma unroll
                    for (int c = 0; c < 16; c++) {
                        int n = nb + c;
                        if (n < Nv)
                            part += tanhf(wb[lane*20 + c] + bias[n]) * proj[n];
                    }
                    atomicAdd(&red[wm*64 + i*16 + lane], part);
                }
                __syncwarp();
            }
        }
        __syncthreads();
        C[(size_t)(m0 + tid) * gridDim.x + blockIdx.x] = red[tid];
    }
}

// ---------------- bias replication (16 identical rows) ------------------------
__global__ void rep_bias(const float* __restrict__ bias, int Nc)
{
    int idx = blockIdx.x * blockDim.x + threadIdx.x;
    if (idx >= 16 * Nc) return;
    d_brep[(idx / Nc) * Gn + (idx % Nc)] = bias[idx % Nc];
}

// ---------------- gather: x bf16 hi/lo + z pos cols bf16 ----------------------
__global__ void gather_x_kernel(const int* __restrict__ tok,
                                const int* __restrict__ wpos,
                                const float* __restrict__ emb,
                                const float* __restrict__ wpe)
{
    int idx = blockIdx.x * blockDim.x + threadIdx.x;
    if (idx >= M1 * DIN1) return;
    int d = idx % DIN1;
    int m = idx / DIN1;
    float v;
    if (d < En) {
        v = emb[(size_t)tok[m] * En + d];
    } else {
        v = wpe[(size_t)wpos[m] * Pn + (d - En)];
        bf16 h, l;
        split_bf16(v, h, l);
        size_t zi = (size_t)m * ZKP + 2*Hn + (d - En);
        g_zhi[zi] = h;
        g_zlo[zi] = l;
    }
    bf16 h, l;
    split_bf16(v, h, l);
    g_xhi[(size_t)m * XKP + d] = h;
    g_xlo[(size_t)m * XKP + d] = l;
}

__global__ void pad_x_kernel()
{
    int idx = blockIdx.x * blockDim.x + threadIdx.x;
    if (idx >= M1 * (XKP - DIN1)) return;
    int m = idx / (XKP - DIN1);
    int k = DIN1 + idx % (XKP - DIN1);
    g_xhi[(size_t)m * XKP + k] = __float2bfloat16(0.f);
    g_xlo[(size_t)m * XKP + k] = __float2bfloat16(0.f);
}

__global__ void pad_z_kernel()
{
    int idx = blockIdx.x * blockDim.x + threadIdx.x;
    if (idx >= M1 * (ZKP - DATT)) return;
    int m = idx / (ZKP - DATT);
    int k = DATT + idx % (ZKP - DATT);
    g_zhi[(size_t)m * ZKP + k] = __float2bfloat16(0.f);
    g_zlo[(size_t)m * ZKP + k] = __float2bfloat16(0.f);
}

// ---------------- weight conversions -------------------------------------------
__global__ void conv_pad(const float* __restrict__ W, bf16* __restrict__ hi,
                         bf16* __restrict__ lo, int rows, int kc, int kp)
{
    int idx = blockIdx.x * blockDim.x + threadIdx.x;
    if (idx >= rows * kp) return;
    int r = idx / kp;
    int k = idx % kp;
    float v = (k < kc) ? W[(size_t)r * kc + k] : 0.f;
    bf16 h, l;
    split_bf16(v, h, l);
    hi[idx] = h;
    lo[idx] = l;
}

__global__ void conv_wt(const float* __restrict__ W, bf16* __restrict__ hi,
                        bf16* __restrict__ lo, int d, int np, int kp)
{
    int idx = blockIdx.x * blockDim.x + threadIdx.x;
    if (idx >= np * kp) return;
    int e = idx / kp;
    int k = idx % kp;
    float v = (e < d && k < d) ? W[(size_t)k * d + e] : 0.f;
    bf16 h, l;
    split_bf16(v, h, l);
    hi[idx] = h;
    lo[idx] = l;
}

// ---------------- transpose (Whh for scans) -------------------------------------
__global__ void transpose_k(const float* __restrict__ W, float* __restrict__ Wt,
                            int Gr, int Kc)
{
    int idx = blockIdx.x * blockDim.x + threadIdx.x;
    if (idx >= Gr * Kc) return;
    int g = idx / Kc;
    int k = idx % Kc;
    Wt[(size_t)k * Gr + g] = W[idx];
}

// ---------------- word BiLSTM scan (8 rows/block) ------------------------------
__global__ __launch_bounds__(256, 1)
void lstm_scan_w(const float* __restrict__ gpre,
                 const float* __restrict__ Wt_f,
                 const float* __restrict__ Wt_b,
                 float* __restrict__ out,
                 bf16* __restrict__ zhi, bf16* __restrict__ zlo,
                 int N, int T, int ostride)
{
    extern __shared__ float dynsm[];
    float* ws = dynsm;
    float* hs = dynsm + 2*8*1024;
    const int tid = threadIdx.x;
    const int nb  = N / 8;
    const int dir = blockIdx.x / nb;
    const int n0  = (blockIdx.x % nb) * 8;
    const float* __restrict__ Wt = dir ? Wt_b : Wt_f;

    float c[8];
#pragma unroll
    for (int r = 0; r < 8; r++) c[r] = 0.f;
    for (int i = tid; i < 256*8; i += 256) hs[i] = 0.f;

#pragma unroll
    for (int i = 0; i < 8; i++) {
        *(float4*)&ws[(tid + 256*i)*4] = *(const float4*)&Wt[(tid + 256*i)*4];
    }
    __syncthreads();

    const int NT = 32;
    for (int step = 0; step < T; step++) {
        const int tt = dir ? (T - 1 - step) : step;
        u64 acc2[4][4];
#pragma unroll
        for (int rp = 0; rp < 4; rp++) {
            size_t b0 = ((size_t)(dir*N + n0 + rp*2    ) * T + tt) * Gn;
            size_t b1 = ((size_t)(dir*N + n0 + rp*2 + 1) * T + tt) * Gn;
#pragma unroll
            for (int g = 0; g < 4; g++) {
                acc2[rp][g] = pack2(gpre[b0 + g*256 + tid], gpre[b1 + g*256 + tid]);
            }
        }
        for (int kt = 0; kt < NT; kt++) {
            const int cur = kt & 1;
            const bool last = (step == T-1) && (kt == NT-1);
            float4 pf[8];
            if (!last) {
                const float* src = &Wt[(size_t)((kt + 1) & 31) * 8192];
#pragma unroll
                for (int i = 0; i < 8; i++) {
                    pf[i] = *(const float4*)&src[(tid + 256*i)*4];
                }
            }
#pragma unroll
            for (int kk = 0; kk < 8; kk++) {
                const int k = kt*8 + kk;
                const float* wrow = &ws[(cur*8 + kk)*1024];
                float w0 = wrow[tid];
                float w1 = wrow[256+tid];
                float w2 = wrow[512+tid];
                float w3 = wrow[768+tid];
                u64 wd0 = pack2(w0,w0);
                u64 wd1 = pack2(w1,w1);
                u64 wd2 = pack2(w2,w2);
                u64 wd3 = pack2(w3,w3);
#pragma unroll
                for (int rp = 0; rp < 4; rp++) {
                    u64 h2 = *(const u64*)&hs[k*8 + rp*2];
                    fma2(acc2[rp][0], h2, wd0);
                    fma2(acc2[rp][1], h2, wd1);
                    fma2(acc2[rp][2], h2, wd2);
                    fma2(acc2[rp][3], h2, wd3);
                }
            }
            if (!last) {
                float* dst = &ws[(cur ^ 1) * 8192];
#pragma unroll
                for (int i = 0; i < 8; i++) {
                    *(float4*)&dst[(tid + 256*i)*4] = pf[i];
                }
            }
            __syncthreads();
        }
#pragma unroll
        for (int rp = 0; rp < 4; rp++) {
            float p0[2];
            float p1[2];
            float p2[2];
            float p3[2];
            unpack2(p0[0], p0[1], acc2[rp][0]);
            unpack2(p1[0], p1[1], acc2[rp][1]);
            unpack2(p2[0], p2[1], acc2[rp][2]);
            unpack2(p3[0], p3[1], acc2[rp][3]);
#pragma unroll
            for (int hh = 0; hh < 2; hh++) {
                int r = rp*2 + hh;
                float iv = sigmoidf(p0[hh]);
                float fv = sigmoidf(p1[hh]);
                float gv = tanhf(p2[hh]);
                float ov = sigmoidf(p3[hh]);
                c[r] = fv * c[r] + iv * gv;
                float hv = ov * tanhf(c[r]);
                hs[tid*8 + r] = hv;
                size_t mrow = (size_t)(n0 + r) * T + tt;
                out[mrow * ostride + dir*256 + tid] = hv;
                bf16 bh, bl;
                split_bf16(hv, bh, bl);
                zhi[mrow * ZKP + dir*256 + tid] = bh;
                zlo[mrow * ZKP + dir*256 + tid] = bl;
            }
        }
        __syncthreads();
    }
}

// ---------------- sentence BiLSTM scan (1 row/block, keeps hT) ------------------
__global__ __launch_bounds__(256, 1)
void lstm_scan_s(const float* __restrict__ gpre,
                 const float* __restrict__ Wt_f,
                 const float* __restrict__ Wt_b,
                 float* __restrict__ out,
                 bf16* __restrict__ zhi, bf16* __restrict__ zlo,
                 float* __restrict__ hT,
                 int N, int T, int ostride)
{
    extern __shared__ float dynsm[];
    float* ws = dynsm;
    float* hs = dynsm + 2*8*1024;
    const int tid = threadIdx.x;
    const int dir = blockIdx.x / N;
    const int n0  = blockIdx.x % N;
    const float* __restrict__ Wt = dir ? Wt_b : Wt_f;

    float c0 = 0.f;
    hs[tid] = 0.f;

#pragma unroll
    for (int i = 0; i < 8; i++) {
        *(float4*)&ws[(tid + 256*i)*4] = *(const float4*)&Wt[(tid + 256*i)*4];
    }
    __syncthreads();

    const int NT = 32;
    for (int step = 0; step < T; step++) {
        const int tt = dir ? (T - 1 - step) : step;
        float acc[4];
        size_t b0 = ((size_t)(dir*N + n0) * T + tt) * Gn;
#pragma unroll
        for (int g = 0; g < 4; g++) {
            acc[g] = gpre[b0 + g*256 + tid];
        }
        for (int kt = 0; kt < NT; kt++) {
            const int cur = kt & 1;
            const bool last = (step == T-1) && (kt == NT-1);
            float4 pf[8];
            if (!last) {
                const float* src = &Wt[(size_t)((kt + 1) & 31) * 8192];
#pragma unroll
                for (int i = 0; i < 8; i++) {
                    pf[i] = *(const float4*)&src[(tid + 256*i)*4];
                }
            }
#pragma unroll
            for (int kk = 0; kk < 8; kk++) {
                const int k = kt*8 + kk;
                const float* wrow = &ws[(cur*8 + kk)*1024];
                float hv = hs[k];
                acc[0] += hv * wrow[tid];
                acc[1] += hv * wrow[256+tid];
                acc[2] += hv * wrow[512+tid];
                acc[3] += hv * wrow[768+tid];
            }
            if (!last) {
                float* dst = &ws[(cur ^ 1) * 8192];
#pragma unroll
                for (int i = 0; i < 8; i++) {
                    *(float4*)&dst[(tid + 256*i)*4] = pf[i];
                }
            }
            __syncthreads();
        }
        float iv = sigmoidf(acc[0]);
        float fv = sigmoidf(acc[1]);
        float gv = tanhf(acc[2]);
        float ov = sigmoidf(acc[3]);
        c0 = fv * c0 + iv * gv;
        float hv = ov * tanhf(c0);
        hs[tid] = hv;
        size_t mrow = (size_t)n0 * T + tt;
        out[mrow * ostride + dir*256 + tid] = hv;
        bf16 bh, bl;
        split_bf16(hv, bh, bl);
        zhi[mrow * ZKP + dir*256 + tid] = bh;
        zlo[mrow * ZKP + dir*256 + tid] = bl;
        if (step == T - 1) {
            hT[((size_t)dir * N + n0) * 256 + tid] = hv;
        }
        __syncthreads();
    }
}

// ---------------- attention glue -----------------------------------------------
__global__ void sum_scores(const float* __restrict__ scp, float* __restrict__ sc,
                           int M, int NB)
{
    int m = blockIdx.x * blockDim.x + threadIdx.x;
    if (m >= M) return;
    float s = 0.f;
    for (int j = 0; j < NB; j++) s += scp[(size_t)m * NB + j];
    sc[m] = s;
}

__global__ void softmax_pool_kernel(const float* __restrict__ sc,
                                    const float* __restrict__ hsrc,
                                    float* __restrict__ outv,
                                    int T, int stride)
{
    __shared__ float a[64];
    __shared__ float inv_s;
    int n = blockIdx.x;
    int tid = threadIdx.x;
    if (tid == 0) {
        float mx = -1e30f;
        for (int t = 0; t < T; t++) mx = fmaxf(mx, sc[n * T + t]);
        float sum = 0.f;
        for (int t = 0; t < T; t++) {
            float e = expf(sc[n * T + t] - mx);
            a[t] = e;
            sum += e;
        }
        inv_s = 1.f / sum;
    }
    __syncthreads();
    float inv = inv_s;
    for (int col = tid; col < 2*Hn; col += blockDim.x) {
        float acc = 0.f;
        for (int t = 0; t < T; t++) {
            acc += a[t] * hsrc[((size_t)n * T + t) * stride + col];
        }
        outv[(size_t)n * (2*Hn) + col] = acc * inv;
    }
}

__global__ void build_sx_kernel(const int* __restrict__ seg,
                                const float* __restrict__ spe)
{
    int idx = blockIdx.x * blockDim.x + threadIdx.x;
    if (idx >= N1 * ZKP) return;
    int d = idx % ZKP;
    int m = idx / ZKP;
    float v;
    if (d < 2*Hn)      v = d_senvec[(size_t)m * (2*Hn) + d];
    else if (d < DATT) v = spe[(size_t)seg[m] * Pn + (d - 2*Hn)];
    else               v = 0.f;
    bf16 h, l;
    split_bf16(v, h, l);
    g_sxhi[idx] = h;
    g_sxlo[idx] = l;
}

__global__ void fill_z2pos(const int* __restrict__ seg, const float* __restrict__ spe)
{
    int idx = blockIdx.x * blockDim.x + threadIdx.x;
    if (idx >= N1 * (ZKP - 2*Hn)) return;
    int m = idx / (ZKP - 2*Hn);
    int d = idx % (ZKP - 2*Hn);
    float v = (d < Pn) ? spe[(size_t)seg[m] * Pn + d] : 0.f;
    bf16 h, l;
    split_bf16(v, h, l);
    g_z2hi[(size_t)m * ZKP + 2*Hn + d] = h;
    g_z2lo[(size_t)m * ZKP + 2*Hn + d] = l;
}

// ---------------- classifier head ------------------------------------------------
__global__ void final_dense_kernel(const float* __restrict__ dW,
                                   const float* __restrict__ db,
                                   float* __restrict__ outp)
{
    __shared__ float r0[128];
    __shared__ float r1[128];
    __shared__ float r2[128];
    int b = blockIdx.x;
    int tid = threadIdx.x;
    float a0 = 0.f, a1 = 0.f, a2 = 0.f;
    for (int k = tid; k < 4*Hn; k += 128) {
        float f;
        if (k < 2*Hn)      f = d_docvec[b * 2*Hn + k];
        else if (k < 3*Hn) f = d_hT[(0 * Bn + b) * Hn + (k - 2*Hn)];
        else               f = d_hT[(1 * Bn + b) * Hn + (k - 3*Hn)];
        a0 += f * dW[0*4*Hn + k];
        a1 += f * dW[1*4*Hn + k];
        a2 += f * dW[2*4*Hn + k];
    }
    r0[tid] = a0;
    r1[tid] = a1;
    r2[tid] = a2;
    __syncthreads();
    for (int s = 64; s > 0; s >>= 1) {
        if (tid < s) {
            r0[tid] += r0[tid+s];
            r1[tid] += r1[tid+s];
            r2[tid] += r2[tid+s];
        }
        __syncthreads();
    }
    if (tid == 0) {
        outp[b*3+0] = r0[0] + db[0];
        outp[b*3+1] = r1[0] + db[1];
        outp[b*3+2] = r2[0] + db[2];
    }
}

// ---------------- host driver ------------------------------------------------------
extern "C" void kernel_launch(void* const* d_in, const int* in_sizes, int n_in,
                              void* d_out, int out_size)
{
    const int*   tok     = (const int*)d_in[0];
    const int*   wpos    = (const int*)d_in[1];
    const int*   seg     = (const int*)d_in[2];
    const float* emb     = (const float*)d_in[3];
    const float* wpe     = (const float*)d_in[4];
    const float* spe     = (const float*)d_in[5];
    const float* wWih_f  = (const float*)d_in[6];
    const float* wWhh_f  = (const float*)d_in[7];
    const float* wb_f    = (const float*)d_in[8];
    const float* wWih_b  = (const float*)d_in[9];
    const float* wWhh_b  = (const float*)d_in[10];
    const float* wb_b    = (const float*)d_in[11];
    const float* sWih_f  = (const float*)d_in[12];
    const float* sWhh_f  = (const float*)d_in[13];
    const float* sb_f    = (const float*)d_in[14];
    const float* sWih_b  = (const float*)d_in[15];
    const float* sWhh_b  = (const float*)d_in[16];
    const float* sb_b    = (const float*)d_in[17];
    const float* word_W  = (const float*)d_in[18];
    const float* word_b  = (const float*)d_in[19];
    const float* word_p  = (const float*)d_in[20];
    const float* sent_W  = (const float*)d_in[21];
    const float* sent_b  = (const float*)d_in[22];
    const float* sent_p  = (const float*)d_in[23];
    const float* dense_W = (const float*)d_in[24];
    const float* dense_b = (const float*)d_in[25];
    float* outp = (float*)d_out;

    float *pgpre, *pz, *pscp, *psc, *psenvec, *pgpre2, *pz2,
          *phT, *pscp2, *psc2, *pdocvec, *pwtf, *pwtb, *pstf, *pstb, *pbrep;
    bf16 *pxhi, *pxlo, *pzhi, *pzlo, *psxhi, *psxlo, *pz2hi, *pz2lo,
         *pwihfh, *pwihfl, *pwihbh, *pwihbl, *psihfh, *psihfl, *psihbh, *psihbl,
         *pwWth, *pwWtl, *psWth, *psWtl;
    cudaGetSymbolAddress((void**)&pgpre,   d_gpre);
    cudaGetSymbolAddress((void**)&pz,      d_z);
    cudaGetSymbolAddress((void**)&pscp,    d_scp);
    cudaGetSymbolAddress((void**)&psc,     d_scores);
    cudaGetSymbolAddress((void**)&psenvec, d_senvec);
    cudaGetSymbolAddress((void**)&pgpre2,  d_gpre2);
    cudaGetSymbolAddress((void**)&pz2,     d_z2);
    cudaGetSymbolAddress((void**)&phT,     d_hT);
    cudaGetSymbolAddress((void**)&pscp2,   d_scp2);
    cudaGetSymbolAddress((void**)&psc2,    d_scores2);
    cudaGetSymbolAddress((void**)&pdocvec, d_docvec);
    cudaGetSymbolAddress((void**)&pwtf,    d_wtf);
    cudaGetSymbolAddress((void**)&pwtb,    d_wtb);
    cudaGetSymbolAddress((void**)&pstf,    d_stf);
    cudaGetSymbolAddress((void**)&pstb,    d_stb);
    cudaGetSymbolAddress((void**)&pbrep,   d_brep);
    cudaGetSymbolAddress((void**)&pxhi,    g_xhi);
    cudaGetSymbolAddress((void**)&pxlo,    g_xlo);
    cudaGetSymbolAddress((void**)&pzhi,    g_zhi);
    cudaGetSymbolAddress((void**)&pzlo,    g_zlo);
    cudaGetSymbolAddress((void**)&psxhi,   g_sxhi);
    cudaGetSymbolAddress((void**)&psxlo,   g_sxlo);
    cudaGetSymbolAddress((void**)&pz2hi,   g_z2hi);
    cudaGetSymbolAddress((void**)&pz2lo,   g_z2lo);
    cudaGetSymbolAddress((void**)&pwihfh,  g_wihf_hi);
    cudaGetSymbolAddress((void**)&pwihfl,  g_wihf_lo);
    cudaGetSymbolAddress((void**)&pwihbh,  g_wihb_hi);
    cudaGetSymbolAddress((void**)&pwihbl,  g_wihb_lo);
    cudaGetSymbolAddress((void**)&psihfh,  g_sihf_hi);
    cudaGetSymbolAddress((void**)&psihfl,  g_sihf_lo);
    cudaGetSymbolAddress((void**)&psihbh,  g_sihb_hi);
    cudaGetSymbolAddress((void**)&psihbl,  g_sihb_lo);
    cudaGetSymbolAddress((void**)&pwWth,   g_wWt_hi);
    cudaGetSymbolAddress((void**)&pwWtl,   g_wWt_lo);
    cudaGetSymbolAddress((void**)&psWth,   g_sWt_hi);
    cudaGetSymbolAddress((void**)&psWtl,   g_sWt_lo);

    cudaFuncSetAttribute(lstm_scan_w, cudaFuncAttributeMaxDynamicSharedMemorySize,
                         2*8*1024*4 + 256*8*4);
    cudaFuncSetAttribute(lstm_scan_s, cudaFuncAttributeMaxDynamicSharedMemorySize,
                         2*8*1024*4 + 256*4);
    cudaFuncSetAttribute(gemm_wb, cudaFuncAttributeMaxDynamicSharedMemorySize,
                         GEMM_SMEM2);

    // 1. gather + padding
    gather_x_kernel<<<(M1*DIN1 + 255)/256, 256>>>(tok, wpos, emb, wpe);
    pad_x_kernel<<<(M1*(XKP-DIN1) + 255)/256, 256>>>();
    pad_z_kernel<<<(M1*(ZKP-DATT) + 255)/256, 256>>>();

    // 2. weight conversions + Whh transposes
    conv_pad<<<(Gn*XKP + 255)/256, 256>>>(wWih_f, pwihfh, pwihfl, Gn, DIN1, XKP);
    conv_pad<<<(Gn*XKP + 255)/256, 256>>>(wWih_b, pwihbh, pwihbl, Gn, DIN1, XKP);
    conv_pad<<<(Gn*ZKP + 255)/256, 256>>>(sWih_f, psihfh, psihfl, Gn, DATT, ZKP);
    conv_pad<<<(Gn*ZKP + 255)/256, 256>>>(sWih_b, psihbh, psihbl, Gn, DATT, ZKP);
    conv_wt<<<(ZKP*ZKP + 255)/256, 256>>>(word_W, pwWth, pwWtl, DATT, ZKP, ZKP);
    conv_wt<<<(ZKP*ZKP + 255)/256, 256>>>(sent_W, psWth, psWtl, DATT, ZKP, ZKP);
    transpose_k<<<(Gn*Hn + 255)/256, 256>>>(wWhh_f, pwtf, Gn, Hn);
    transpose_k<<<(Gn*Hn + 255)/256, 256>>>(wWhh_b, pwtb, Gn, Hn);
    transpose_k<<<(Gn*Hn + 255)/256, 256>>>(sWhh_f, pstf, Gn, Hn);
    transpose_k<<<(Gn*Hn + 255)/256, 256>>>(sWhh_b, pstb, Gn, Hn);

    // 3. word input GEMMs
    {
        dim3 g(Gn/128, M1/256);
        rep_bias<<<(16*Gn + 255)/256, 256>>>(wb_f, Gn);
        gemm_wb<<<g, 256, GEMM_SMEM2>>>(pxhi, pxlo, pwihfh, pwihfl, pbrep,
                                        (const float*)0, (const float*)0,
                                        pgpre, M1, Gn, XKP, Gn, 0);
        rep_bias<<<(16*Gn + 255)/256, 256>>>(wb_b, Gn);
        gemm_wb<<<g, 256, GEMM_SMEM2>>>(pxhi, pxlo, pwihbh, pwihbl, pbrep,
                                        (const float*)0, (const float*)0,
                                        pgpre + (size_t)M1*Gn, M1, Gn, XKP, Gn, 0);
    }

    // 4. word BiLSTM scan -> d_z fp32 + z bf16
    lstm_scan_w<<<128, 256, 2*8*1024*4 + 256*8*4>>>(pgpre, pwtf, pwtb, pz,
                                                    pzhi, pzlo, N1, Ln, DATT);

    // 5. word attention
    gemm_wb<<<dim3(NBATT, M1/256), 256, GEMM_SMEM2>>>(pzhi, pzlo, pwWth, pwWtl,
                                                      (const float*)0, word_b, word_p,
                                                      pscp, M1, ZKP, ZKP, DATT, 1);
    sum_scores<<<(M1 + 255)/256, 256>>>(pscp, psc, M1, NBATT);
    softmax_pool_kernel<<<N1, 256>>>(psc, pz, psenvec, Ln, DATT);

    // 6. sentence input
    build_sx_kernel<<<(N1*ZKP + 255)/256, 256>>>(seg, spe);
    fill_z2pos<<<(N1*(ZKP-2*Hn) + 255)/256, 256>>>(seg, spe);
    {
        dim3 g(Gn/128, N1/256);
        rep_bias<<<(16*Gn + 255)/256, 256>>>(sb_f, Gn);
        gemm_wb<<<g, 256, GEMM_SMEM2>>>(psxhi, psxlo, psihfh, psihfl, pbrep,
                                        (const float*)0, (const float*)0,
                                        pgpre2, N1, Gn, ZKP, Gn, 0);
        rep_bias<<<(16*Gn + 255)/256, 256>>>(sb_b, Gn);
        gemm_wb<<<g, 256, GEMM_SMEM2>>>(psxhi, psxlo, psihbh, psihbl, pbrep,
                                        (const float*)0, (const float*)0,
                                        pgpre2 + (size_t)N1*Gn, N1, Gn, ZKP, Gn, 0);
    }

    // 7. sentence BiLSTM scan -> d_z2 fp32 + z2 bf16, keeps hT
    lstm_scan_s<<<2*Bn, 256, 2*8*1024*4 + 256*4>>>(pgpre2, pstf, pstb, pz2,
                                                   pz2hi, pz2lo, phT, Bn, Sn, DATT);

    // 8. sentence attention
    gemm_wb<<<dim3(NBATT, N1/256), 256, GEMM_SMEM2>>>(pz2hi, pz2lo, psWth, psWtl,
                                                      (const float*)0, sent_b, sent_p,
                                                      pscp2, N1, ZKP, ZKP, DATT, 1);
    sum_scores<<<(N1 + 255)/256, 256>>>(pscp2, psc2, N1, NBATT);
    softmax_pool_kernel<<<Bn, 256>>>(psc2, pz2, pdocvec, Sn, DATT);

    // 9. classifier head
    final_dense_kernel<<<Bn, 128>>>(dense_W, dense_b, outp);
}

// round 14
// speedup vs baseline: 1.1358x; 1.1358x over previous
#include <cuda_runtime.h>
#include <cuda_bf16.h>
#include <mma.h>
#include <cstdint>
#include <math.h>

using namespace nvcuda;

// ---------------- problem constants ----------------
#define Bn   32
#define Sn   16
#define Ln   64
#define En   300
#define Pn   100
#define Hn   256
#define Gn   1024
#define DATT 612
#define N1   (Bn*Sn)
#define M1   (N1*Ln)
#define DIN1 (En+Pn)
#define NBATT 5             // 640/128
#define XKP  416            // padded K for x (400)
#define ZKP  640            // padded K/N for 612

typedef unsigned long long u64;
typedef __nv_bfloat16 bf16;

// ---------------- scratch (device globals) ----------------------------------
__device__ float d_gpre[2*M1*Gn];
__device__ float d_z[M1*DATT];
__device__ float d_scp[M1*NBATT];
__device__ float d_scores[M1];
__device__ float d_senvec[N1*2*Hn];
__device__ float d_gpre2[2*N1*Gn];
__device__ float d_z2[N1*DATT];
__device__ float d_hT[2*Bn*Hn];
__device__ float d_scp2[N1*NBATT];
__device__ float d_scores2[N1];
__device__ float d_docvec[Bn*2*Hn];
__device__ float d_wtf[Hn*Gn];
__device__ float d_wtb[Hn*Gn];
__device__ float d_stf[Hn*Gn];
__device__ float d_stb[Hn*Gn];
__device__ float d_brep[16*Gn];     // replicated bias (16 identical rows)
__device__ bf16 g_xhi[M1*XKP];
__device__ bf16 g_xlo[M1*XKP];
__device__ bf16 g_zhi[(size_t)M1*ZKP];
__device__ bf16 g_zlo[(size_t)M1*ZKP];
__device__ bf16 g_sxhi[N1*ZKP];
__device__ bf16 g_sxlo[N1*ZKP];
__device__ bf16 g_z2hi[N1*ZKP];
__device__ bf16 g_z2lo[N1*ZKP];
__device__ bf16 g_wihf_hi[Gn*XKP];
__device__ bf16 g_wihf_lo[Gn*XKP];
__device__ bf16 g_wihb_hi[Gn*XKP];
__device__ bf16 g_wihb_lo[Gn*XKP];
__device__ bf16 g_sihf_hi[Gn*ZKP];
__device__ bf16 g_sihf_lo[Gn*ZKP];
__device__ bf16 g_sihb_hi[Gn*ZKP];
__device__ bf16 g_sihb_lo[Gn*ZKP];
__device__ bf16 g_wWt_hi[ZKP*ZKP];
__device__ bf16 g_wWt_lo[ZKP*ZKP];
__device__ bf16 g_sWt_hi[ZKP*ZKP];
__device__ bf16 g_sWt_lo[ZKP*ZKP];

__device__ __forceinline__ float sigmoidf(float x) { return 1.0f / (1.0f + expf(-x)); }

__device__ __forceinline__ void fma2(u64& d, u64 a, u64 b) {
    asm("fma.rn.f32x2 %0, %1, %2, %3;" : "=l"(d) : "l"(a), "l"(b), "l"(d));
}
__device__ __forceinline__ u64 pack2(float x, float y) {
    u64 r; asm("mov.b64 %0, {%1,%2};" : "=l"(r) : "f"(x), "f"(y)); return r;
}
__device__ __forceinline__ void unpack2(float& lo, float& hi, u64 v) {
    asm("mov.b64 {%0,%1}, %2;" : "=f"(lo), "=f"(hi) : "l"(v));
}
__device__ __forceinline__ void split_bf16(float v, bf16& h, bf16& l) {
    h = __float2bfloat16(v);
    l = __float2bfloat16(v - __bfloat162float(h));
}
__device__ __forceinline__ uint32_t smem_u32(const void* p) {
    return (uint32_t)__cvta_generic_to_shared(p);
}
__device__ __forceinline__ void cp16(uint32_t dst, const void* src) {
    asm volatile("cp.async.cg.shared.global [%0], [%1], 16;" :: "r"(dst), "l"(src));
}
#define CP_COMMIT() asm volatile("cp.async.commit_group;" ::: "memory")
#define CP_WAIT0()  asm volatile("cp.async.wait_group 0;" ::: "memory")

// ======================= WMMA split-bf16 GEMM, 128x128 tile ==================
// C[M,Nc] = A[M,KP] @ B[*,KP]^T, pre-split bf16 hi/lo, KP mult of 32,
// M mult 128, Nc mult 128. cp.async double buffer, K-step 32.
// Tiles padded to 40-elem (80B) rows -> conflict-free LDSM. 2 CTAs/SM.
// attn==0: accumulators init from d_brep (bias, ldm Gn) -> direct global store.
// attn!=0: smem out tile + tanh/proj row-reduction ->
//          C[m*gridDim.x + bx] = sum_{n<Nv} tanh(acc+bias[n])*proj[n]
#define TSE   5120            // tile stride, elems
#define SSE   20480           // stage stride, elems
#define GEMM_SMEM2 82944

__global__ __launch_bounds__(256, 2)
void gemm_wb(const bf16* __restrict__ Ahi, const bf16* __restrict__ Alo,
             const bf16* __restrict__ Bhi, const bf16* __restrict__ Blo,
             const float* __restrict__ brep, const float* __restrict__ bias,
             const float* __restrict__ proj,
             float* __restrict__ C, int M, int Nc, int KP, int Nv, int attn)
{
    extern __shared__ float dynsm[];
    bf16* sb    = (bf16*)dynsm;      // staged tiles
    float* outs = dynsm;             // reused after mainloop (attn path)
    float* red  = dynsm + 20480;     // byte 81920

    const int tid = threadIdx.x;
    const int m0 = blockIdx.y * 128;
    const int n0 = blockIdx.x * 128;
    const int w  = tid >> 5;
    const int wm = w >> 1;           // 0..3  (32-row band)
    const int wn = w & 1;            // 0..1  (64-col band)

    wmma::fragment<wmma::accumulator, 16, 16, 16, float> acc[2][4];
    if (attn == 0) {
#pragma unroll
        for (int i = 0; i < 2; i++)
#pragma unroll
            for (int j = 0; j < 4; j++)
                wmma::load_matrix_sync(acc[i][j], brep + n0 + wn*64 + j*16, Gn,
                                       wmma::mem_row_major);
    } else {
#pragma unroll
        for (int i = 0; i < 2; i++)
#pragma unroll
            for (int j = 0; j < 4; j++)
                wmma::fill_fragment(acc[i][j], 0.0f);
    }

    const int nk   = KP / 32;
    const int rowi = tid >> 1;               // 0..127
    const int kof  = (tid & 1) * 16;         // bf16 elems
    const uint32_t sbase = smem_u32(sb);
    const uint32_t boff  = (uint32_t)(rowi * 80 + kof * 2);   // bytes in tile

    const bf16* __restrict__ pah = Ahi + (size_t)(m0 + rowi) * KP + kof;
    const bf16* __restrict__ pal = Alo + (size_t)(m0 + rowi) * KP + kof;
    const bf16* __restrict__ pbh = Bhi + (size_t)(n0 + rowi) * KP + kof;
    const bf16* __restrict__ pbl = Blo + (size_t)(n0 + rowi) * KP + kof;

    // stage chunk 0 into buffer 0
    {
        const uint32_t d0 = sbase + boff;
        cp16(d0 +     0, pah);     cp16(d0 +    16, pah + 8);
        cp16(d0 + 10240, pal);     cp16(d0 + 10240 + 16, pal + 8);
        cp16(d0 + 20480, pbh);     cp16(d0 + 20480 + 16, pbh + 8);
        cp16(d0 + 30720, pbl);     cp16(d0 + 30720 + 16, pbl + 8);
        CP_COMMIT();
        CP_WAIT0();
    }
    __syncthreads();

    for (int kc = 0; kc < nk; kc++) {
        const int cur = kc & 1;
        if (kc + 1 < nk) {
            const int go = (kc + 1) * 32;
            const uint32_t d1 = sbase + (uint32_t)((cur ^ 1) * 40960) + boff;
            cp16(d1 +     0, pah + go);     cp16(d1 +    16, pah + go + 8);
            cp16(d1 + 10240, pal + go);     cp16(d1 + 10240 + 16, pal + go + 8);
            cp16(d1 + 20480, pbh + go);     cp16(d1 + 20480 + 16, pbh + go + 8);
            cp16(d1 + 30720, pbl + go);     cp16(d1 + 30720 + 16, pbl + go + 8);
            CP_COMMIT();
        }
        const bf16* Ah = sb + cur * SSE;
        const bf16* Al = Ah + TSE;
        const bf16* Bh = Ah + 2 * TSE;
        const bf16* Bl = Ah + 3 * TSE;
#pragma unroll
        for (int kf = 0; kf < 2; kf++) {
            wmma::fragment<wmma::matrix_a, 16, 16, 16, bf16, wmma::row_major> ah[2], al[2];
#pragma unroll
            for (int i = 0; i < 2; i++) {
                wmma::load_matrix_sync(ah[i], Ah + (wm*32 + i*16)*40 + kf*16, 40);
                wmma::load_matrix_sync(al[i], Al + (wm*32 + i*16)*40 + kf*16, 40);
            }
#pragma unroll
            for (int j = 0; j < 4; j++) {
                wmma::fragment<wmma::matrix_b, 16, 16, 16, bf16, wmma::col_major> bh, bl;
                wmma::load_matrix_sync(bh, Bh + (wn*64 + j*16)*40 + kf*16, 40);
                wmma::load_matrix_sync(bl, Bl + (wn*64 + j*16)*40 + kf*16, 40);
#pragma unroll
                for (int i = 0; i < 2; i++) {
                    wmma::mma_sync(acc[i][j], ah[i], bh, acc[i][j]);
                    wmma::mma_sync(acc[i][j], ah[i], bl, acc[i][j]);
                    wmma::mma_sync(acc[i][j], al[i], bh, acc[i][j]);
                }
            }
        }
        if (kc + 1 < nk) CP_WAIT0();
        __syncthreads();
    }

    if (attn == 0) {
        // direct global store (bias already in accumulators)
#pragma unroll
        for (int i = 0; i < 2; i++)
#pragma unroll
            for (int j = 0; j < 4; j++)
                wmma::store_matrix_sync(
                    C + (size_t)(m0 + wm*32 + i*16) * Nc + n0 + wn*64 + j*16,
                    acc[i][j], Nc, wmma::mem_row_major);
    } else {
        // epilogue: reuse smem as fp32 out tile [128][128]
#pragma unroll
        for (int i = 0; i < 2; i++)
#pragma unroll
            for (int j = 0; j < 4; j++)
                wmma::store_matrix_sync(outs + (size_t)(wm*32 + i*16)*128 + wn*64 + j*16,
                                        acc[i][j], 128, wmma::mem_row_major);
        __syncthreads();
        const int row = tid >> 1;
        const int hf  = (tid & 1) * 64;
        float part = 0.f;
#pragma unroll
        for (int c = 0; c < 64; c++) {
            int n = n0 + hf + c;
            if (n < Nv) part += tanhf(outs[row*128 + hf + c] + bias[n]) * proj[n];
        }
        red[tid] = part;
        __syncthreads();
        if (tid < 128) {
            C[(size_t)(m0 + tid) * gridDim.x + blockIdx.x] = red[2*tid] + red[2*tid + 1];
        }
    }
}

// ---------------- bias replication (16 identical rows) ------------------------
__global__ void rep_bias(const float* __restrict__ bias, int Nc)
{
    int idx = blockIdx.x * blockDim.x + threadIdx.x;
    if (idx >= 16 * Nc) return;
    d_brep[(idx / Nc) * Gn + (idx % Nc)] = bias[idx % Nc];
}

// ---------------- gather: x bf16 hi/lo + z pos cols bf16 ----------------------
__global__ void gather_x_kernel(const int* __restrict__ tok,
                                const int* __restrict__ wpos,
                                const float* __restrict__ emb,
                                const float* __restrict__ wpe)
{
    int idx = blockIdx.x * blockDim.x + threadIdx.x;
    if (idx >= M1 * DIN1) return;
    int d = idx % DIN1;
    int m = idx / DIN1;
    float v;
    if (d < En) {
        v = emb[(size_t)tok[m] * En + d];
    } else {
        v = wpe[(size_t)wpos[m] * Pn + (d - En)];
        bf16 h, l;
        split_bf16(v, h, l);
        size_t zi = (size_t)m * ZKP + 2*Hn + (d - En);
        g_zhi[zi] = h;
        g_zlo[zi] = l;
    }
    bf16 h, l;
    split_bf16(v, h, l);
    g_xhi[(size_t)m * XKP + d] = h;
    g_xlo[(size_t)m * XKP + d] = l;
}

__global__ void pad_x_kernel()
{
    int idx = blockIdx.x * blockDim.x + threadIdx.x;
    if (idx >= M1 * (XKP - DIN1)) return;
    int m = idx / (XKP - DIN1);
    int k = DIN1 + idx % (XKP - DIN1);
    g_xhi[(size_t)m * XKP + k] = __float2bfloat16(0.f);
    g_xlo[(size_t)m * XKP + k] = __float2bfloat16(0.f);
}

__global__ void pad_z_kernel()
{
    int idx = blockIdx.x * blockDim.x + threadIdx.x;
    if (idx >= M1 * (ZKP - DATT)) return;
    int m = idx / (ZKP - DATT);
    int k = DATT + idx % (ZKP - DATT);
    g_zhi[(size_t)m * ZKP + k] = __float2bfloat16(0.f);
    g_zlo[(size_t)m * ZKP + k] = __float2bfloat16(0.f);
}

// ---------------- weight conversions -------------------------------------------
__global__ void conv_pad(const float* __restrict__ W, bf16* __restrict__ hi,
                         bf16* __restrict__ lo, int rows, int kc, int kp)
{
    int idx = blockIdx.x * blockDim.x + threadIdx.x;
    if (idx >= rows * kp) return;
    int r = idx / kp;
    int k = idx % kp;
    float v = (k < kc) ? W[(size_t)r * kc + k] : 0.f;
    bf16 h, l;
    split_bf16(v, h, l);
    hi[idx] = h;
    lo[idx] = l;
}

__global__ void conv_wt(const float* __restrict__ W, bf16* __restrict__ hi,
                        bf16* __restrict__ lo, int d, int np, int kp)
{
    int idx = blockIdx.x * blockDim.x + threadIdx.x;
    if (idx >= np * kp) return;
    int e = idx / kp;
    int k = idx % kp;
    float v = (e < d && k < d) ? W[(size_t)k * d + e] : 0.f;
    bf16 h, l;
    split_bf16(v, h, l);
    hi[idx] = h;
    lo[idx] = l;
}

// ---------------- transpose (Whh for scans) -------------------------------------
__global__ void transpose_k(const float* __restrict__ W, float* __restrict__ Wt,
                            int Gr, int Kc)
{
    int idx = blockIdx.x * blockDim.x + threadIdx.x;
    if (idx >= Gr * Kc) return;
    int g = idx / Kc;
    int k = idx % Kc;
    Wt[(size_t)k * Gr + g] = W[idx];
}

// ---------------- word BiLSTM scan (8 rows/block) ------------------------------
__global__ __launch_bounds__(256, 1)
void lstm_scan_w(const float* __restrict__ gpre,
                 const float* __restrict__ Wt_f,
                 const float* __restrict__ Wt_b,
                 float* __restrict__ out,
                 bf16* __restrict__ zhi, bf16* __restrict__ zlo,
                 int N, int T, int ostride)
{
    extern __shared__ float dynsm[];
    float* ws = dynsm;
    float* hs = dynsm + 2*8*1024;
    const int tid = threadIdx.x;
    const int nb  = N / 8;
    const int dir = blockIdx.x / nb;
    const int n0  = (blockIdx.x % nb) * 8;
    const float* __restrict__ Wt = dir ? Wt_b : Wt_f;

    float c[8];
#pragma unroll
    for (int r = 0; r < 8; r++) c[r] = 0.f;
    for (int i = tid; i < 256*8; i += 256) hs[i] = 0.f;

#pragma unroll
    for (int i = 0; i < 8; i++) {
        *(float4*)&ws[(tid + 256*i)*4] = *(const float4*)&Wt[(tid + 256*i)*4];
    }
    __syncthreads();

    const int NT = 32;
    for (int step = 0; step < T; step++) {
        const int tt = dir ? (T - 1 - step) : step;
        u64 acc2[4][4];
#pragma unroll
        for (int rp = 0; rp < 4; rp++) {
            size_t b0 = ((size_t)(dir*N + n0 + rp*2    ) * T + tt) * Gn;
            size_t b1 = ((size_t)(dir*N + n0 + rp*2 + 1) * T + tt) * Gn;
#pragma unroll
            for (int g = 0; g < 4; g++) {
                acc2[rp][g] = pack2(gpre[b0 + g*256 + tid], gpre[b1 + g*256 + tid]);
            }
        }
        for (int kt = 0; kt < NT; kt++) {
            const int cur = kt & 1;
            const bool last = (step == T-1) && (kt == NT-1);
            float4 pf[8];
            if (!last) {
                const float* src = &Wt[(size_t)((kt + 1) & 31) * 8192];
#pragma unroll
                for (int i = 0; i < 8; i++) {
                    pf[i] = *(const float4*)&src[(tid + 256*i)*4];
                }
            }
#pragma unroll
            for (int kk = 0; kk < 8; kk++) {
                const int k = kt*8 + kk;
                const float* wrow = &ws[(cur*8 + kk)*1024];
                float w0 = wrow[tid];
                float w1 = wrow[256+tid];
                float w2 = wrow[512+tid];
                float w3 = wrow[768+tid];
                u64 wd0 = pack2(w0,w0);
                u64 wd1 = pack2(w1,w1);
                u64 wd2 = pack2(w2,w2);
                u64 wd3 = pack2(w3,w3);
#pragma unroll
                for (int rp = 0; rp < 4; rp++) {
                    u64 h2 = *(const u64*)&hs[k*8 + rp*2];
                    fma2(acc2[rp][0], h2, wd0);
                    fma2(acc2[rp][1], h2, wd1);
                    fma2(acc2[rp][2], h2, wd2);
                    fma2(acc2[rp][3], h2, wd3);
                }
            }
            if (!last) {
                float* dst = &ws[(cur ^ 1) * 8192];
#pragma unroll
                for (int i = 0; i < 8; i++) {
                    *(float4*)&dst[(tid + 256*i)*4] = pf[i];
                }
            }
            __syncthreads();
        }
#pragma unroll
        for (int rp = 0; rp < 4; rp++) {
            float p0[2];
            float p1[2];
            float p2[2];
            float p3[2];
            unpack2(p0[0], p0[1], acc2[rp][0]);
            unpack2(p1[0], p1[1], acc2[rp][1]);
            unpack2(p2[0], p2[1], acc2[rp][2]);
            unpack2(p3[0], p3[1], acc2[rp][3]);
#pragma unroll
            for (int hh = 0; hh < 2; hh++) {
                int r = rp*2 + hh;
                float iv = sigmoidf(p0[hh]);
                float fv = sigmoidf(p1[hh]);
                float gv = tanhf(p2[hh]);
                float ov = sigmoidf(p3[hh]);
                c[r] = fv * c[r] + iv * gv;
                float hv = ov * tanhf(c[r]);
                hs[tid*8 + r] = hv;
                size_t mrow = (size_t)(n0 + r) * T + tt;
                out[mrow * ostride + dir*256 + tid] = hv;
                bf16 bh, bl;
                split_bf16(hv, bh, bl);
                zhi[mrow * ZKP + dir*256 + tid] = bh;
                zlo[mrow * ZKP + dir*256 + tid] = bl;
            }
        }
        __syncthreads();
    }
}

// ---------------- sentence BiLSTM scan (1 row/block, keeps hT) ------------------
__global__ __launch_bounds__(256, 1)
void lstm_scan_s(const float* __restrict__ gpre,
                 const float* __restrict__ Wt_f,
                 const float* __restrict__ Wt_b,
                 float* __restrict__ out,
                 bf16* __restrict__ zhi, bf16* __restrict__ zlo,
                 float* __restrict__ hT,
                 int N, int T, int ostride)
{
    extern __shared__ float dynsm[];
    float* ws = dynsm;
    float* hs = dynsm + 2*8*1024;
    const int tid = threadIdx.x;
    const int dir = blockIdx.x / N;
    const int n0  = blockIdx.x % N;
    const float* __restrict__ Wt = dir ? Wt_b : Wt_f;

    float c0 = 0.f;
    hs[tid] = 0.f;

#pragma unroll
    for (int i = 0; i < 8; i++) {
        *(float4*)&ws[(tid + 256*i)*4] = *(const float4*)&Wt[(tid + 256*i)*4];
    }
    __syncthreads();

    const int NT = 32;
    for (int step = 0; step < T; step++) {
        const int tt = dir ? (T - 1 - step) : step;
        float acc[4];
        size_t b0 = ((size_t)(dir*N + n0) * T + tt) * Gn;
#pragma unroll
        for (int g = 0; g < 4; g++) {
            acc[g] = gpre[b0 + g*256 + tid];
        }
        for (int kt = 0; kt < NT; kt++) {
            const int cur = kt & 1;
            const bool last = (step == T-1) && (kt == NT-1);
            float4 pf[8];
            if (!last) {
                const float* src = &Wt[(size_t)((kt + 1) & 31) * 8192];
#pragma unroll
                for (int i = 0; i < 8; i++) {
                    pf[i] = *(const float4*)&src[(tid + 256*i)*4];
                }
            }
#pragma unroll
            for (int kk = 0; kk < 8; kk++) {
                const int k = kt*8 + kk;
                const float* wrow = &ws[(cur*8 + kk)*1024];
                float hv = hs[k];
                acc[0] += hv * wrow[tid];
                acc[1] += hv * wrow[256+tid];
                acc[2] += hv * wrow[512+tid];
                acc[3] += hv * wrow[768+tid];
            }
            if (!last) {
                float* dst = &ws[(cur ^ 1) * 8192];
#pragma unroll
                for (int i = 0; i < 8; i++) {
                    *(float4*)&dst[(tid + 256*i)*4] = pf[i];
                }
            }
            __syncthreads();
        }
        float iv = sigmoidf(acc[0]);
        float fv = sigmoidf(acc[1]);
        float gv = tanhf(acc[2]);
        float ov = sigmoidf(acc[3]);
        c0 = fv * c0 + iv * gv;
        float hv = ov * tanhf(c0);
        hs[tid] = hv;
        size_t mrow = (size_t)n0 * T + tt;
        out[mrow * ostride + dir*256 + tid] = hv;
        bf16 bh, bl;
        split_bf16(hv, bh, bl);
        zhi[mrow * ZKP + dir*256 + tid] = bh;
        zlo[mrow * ZKP + dir*256 + tid] = bl;
        if (step == T - 1) {
            hT[((size_t)dir * N + n0) * 256 + tid] = hv;
        }
        __syncthreads();
    }
}

// ---------------- attention glue -----------------------------------------------
__global__ void sum_scores(const float* __restrict__ scp, float* __restrict__ sc,
                           int M, int NB)
{
    int m = blockIdx.x * blockDim.x + threadIdx.x;
    if (m >= M) return;
    float s = 0.f;
    for (int j = 0; j < NB; j++) s += scp[(size_t)m * NB + j];
    sc[m] = s;
}

__global__ void softmax_pool_kernel(const float* __restrict__ sc,
                                    const float* __restrict__ hsrc,
                                    float* __restrict__ outv,
                                    int T, int stride)
{
    __shared__ float a[64];
    __shared__ float inv_s;
    int n = blockIdx.x;
    int tid = threadIdx.x;
    if (tid == 0) {
        float mx = -1e30f;
        for (int t = 0; t < T; t++) mx = fmaxf(mx, sc[n * T + t]);
        float sum = 0.f;
        for (int t = 0; t < T; t++) {
            float e = expf(sc[n * T + t] - mx);
            a[t] = e;
            sum += e;
        }
        inv_s = 1.f / sum;
    }
    __syncthreads();
    float inv = inv_s;
    for (int col = tid; col < 2*Hn; col += blockDim.x) {
        float acc = 0.f;
        for (int t = 0; t < T; t++) {
            acc += a[t] * hsrc[((size_t)n * T + t) * stride + col];
        }
        outv[(size_t)n * (2*Hn) + col] = acc * inv;
    }
}

__global__ void build_sx_kernel(const int* __restrict__ seg,
                                const float* __restrict__ spe)
{
    int idx = blockIdx.x * blockDim.x + threadIdx.x;
    if (idx >= N1 * ZKP) return;
    int d = idx % ZKP;
    int m = idx / ZKP;
    float v;
    if (d < 2*Hn)      v = d_senvec[(size_t)m * (2*Hn) + d];
    else if (d < DATT) v = spe[(size_t)seg[m] * Pn + (d - 2*Hn)];
    else               v = 0.f;
    bf16 h, l;
    split_bf16(v, h, l);
    g_sxhi[idx] = h;
    g_sxlo[idx] = l;
}

__global__ void fill_z2pos(const int* __restrict__ seg, const float* __restrict__ spe)
{
    int idx = blockIdx.x * blockDim.x + threadIdx.x;
    if (idx >= N1 * (ZKP - 2*Hn)) return;
    int m = idx / (ZKP - 2*Hn);
    int d = idx % (ZKP - 2*Hn);
    float v = (d < Pn) ? spe[(size_t)seg[m] * Pn + d] : 0.f;
    bf16 h, l;
    split_bf16(v, h, l);
    g_z2hi[(size_t)m * ZKP + 2*Hn + d] = h;
    g_z2lo[(size_t)m * ZKP + 2*Hn + d] = l;
}

// ---------------- classifier head ------------------------------------------------
__global__ void final_dense_kernel(const float* __restrict__ dW,
                                   const float* __restrict__ db,
                                   float* __restrict__ outp)
{
    __shared__ float r0[128];
    __shared__ float r1[128];
    __shared__ float r2[128];
    int b = blockIdx.x;
    int tid = threadIdx.x;
    float a0 = 0.f, a1 = 0.f, a2 = 0.f;
    for (int k = tid; k < 4*Hn; k += 128) {
        float f;
        if (k < 2*Hn)      f = d_docvec[b * 2*Hn + k];
        else if (k < 3*Hn) f = d_hT[(0 * Bn + b) * Hn + (k - 2*Hn)];
        else               f = d_hT[(1 * Bn + b) * Hn + (k - 3*Hn)];
        a0 += f * dW[0*4*Hn + k];
        a1 += f * dW[1*4*Hn + k];
        a2 += f * dW[2*4*Hn + k];
    }
    r0[tid] = a0;
    r1[tid] = a1;
    r2[tid] = a2;
    __syncthreads();
    for (int s = 64; s > 0; s >>= 1) {
        if (tid < s) {
            r0[tid] += r0[tid+s];
            r1[tid] += r1[tid+s];
            r2[tid] += r2[tid+s];
        }
        __syncthreads();
    }
    if (tid == 0) {
        outp[b*3+0] = r0[0] + db[0];
        outp[b*3+1] = r1[0] + db[1];
        outp[b*3+2] = r2[0] + db[2];
    }
}

// ---------------- host driver ------------------------------------------------------
extern "C" void kernel_launch(void* const* d_in, const int* in_sizes, int n_in,
                              void* d_out, int out_size)
{
    const int*   tok     = (const int*)d_in[0];
    const int*   wpos    = (const int*)d_in[1];
    const int*   seg     = (const int*)d_in[2];
    const float* emb     = (const float*)d_in[3];
    const float* wpe     = (const float*)d_in[4];
    const float* spe     = (const float*)d_in[5];
    const float* wWih_f  = (const float*)d_in[6];
    const float* wWhh_f  = (const float*)d_in[7];
    const float* wb_f    = (const float*)d_in[8];
    const float* wWih_b  = (const float*)d_in[9];
    const float* wWhh_b  = (const float*)d_in[10];
    const float* wb_b    = (const float*)d_in[11];
    const float* sWih_f  = (const float*)d_in[12];
    const float* sWhh_f  = (const float*)d_in[13];
    const float* sb_f    = (const float*)d_in[14];
    const float* sWih_b  = (const float*)d_in[15];
    const float* sWhh_b  = (const float*)d_in[16];
    const float* sb_b    = (const float*)d_in[17];
    const float* word_W  = (const float*)d_in[18];
    const float* word_b  = (const float*)d_in[19];
    const float* word_p  = (const float*)d_in[20];
    const float* sent_W  = (const float*)d_in[21];
    const float* sent_b  = (const float*)d_in[22];
    const float* sent_p  = (const float*)d_in[23];
    const float* dense_W = (const float*)d_in[24];
    const float* dense_b = (const float*)d_in[25];
    float* outp = (float*)d_out;

    float *pgpre, *pz, *pscp, *psc, *psenvec, *pgpre2, *pz2,
          *phT, *pscp2, *psc2, *pdocvec, *pwtf, *pwtb, *pstf, *pstb, *pbrep;
    bf16 *pxhi, *pxlo, *pzhi, *pzlo, *psxhi, *psxlo, *pz2hi, *pz2lo,
         *pwihfh, *pwihfl, *pwihbh, *pwihbl, *psihfh, *psihfl, *psihbh, *psihbl,
         *pwWth, *pwWtl, *psWth, *psWtl;
    cudaGetSymbolAddress((void**)&pgpre,   d_gpre);
    cudaGetSymbolAddress((void**)&pz,      d_z);
    cudaGetSymbolAddress((void**)&pscp,    d_scp);
    cudaGetSymbolAddress((void**)&psc,     d_scores);
    cudaGetSymbolAddress((void**)&psenvec, d_senvec);
    cudaGetSymbolAddress((void**)&pgpre2,  d_gpre2);
    cudaGetSymbolAddress((void**)&pz2,     d_z2);
    cudaGetSymbolAddress((void**)&phT,     d_hT);
    cudaGetSymbolAddress((void**)&pscp2,   d_scp2);
    cudaGetSymbolAddress((void**)&psc2,    d_scores2);
    cudaGetSymbolAddress((void**)&pdocvec, d_docvec);
    cudaGetSymbolAddress((void**)&pwtf,    d_wtf);
    cudaGetSymbolAddress((void**)&pwtb,    d_wtb);
    cudaGetSymbolAddress((void**)&pstf,    d_stf);
    cudaGetSymbolAddress((void**)&pstb,    d_stb);
    cudaGetSymbolAddress((void**)&pbrep,   d_brep);
    cudaGetSymbolAddress((void**)&pxhi,    g_xhi);
    cudaGetSymbolAddress((void**)&pxlo,    g_xlo);
    cudaGetSymbolAddress((void**)&pzhi,    g_zhi);
    cudaGetSymbolAddress((void**)&pzlo,    g_zlo);
    cudaGetSymbolAddress((void**)&psxhi,   g_sxhi);
    cudaGetSymbolAddress((void**)&psxlo,   g_sxlo);
    cudaGetSymbolAddress((void**)&pz2hi,   g_z2hi);
    cudaGetSymbolAddress((void**)&pz2lo,   g_z2lo);
    cudaGetSymbolAddress((void**)&pwihfh,  g_wihf_hi);
    cudaGetSymbolAddress((void**)&pwihfl,  g_wihf_lo);
    cudaGetSymbolAddress((void**)&pwihbh,  g_wihb_hi);
    cudaGetSymbolAddress((void**)&pwihbl,  g_wihb_lo);
    cudaGetSymbolAddress((void**)&psihfh,  g_sihf_hi);
    cudaGetSymbolAddress((void**)&psihfl,  g_sihf_lo);
    cudaGetSymbolAddress((void**)&psihbh,  g_sihb_hi);
    cudaGetSymbolAddress((void**)&psihbl,  g_sihb_lo);
    cudaGetSymbolAddress((void**)&pwWth,   g_wWt_hi);
    cudaGetSymbolAddress((void**)&pwWtl,   g_wWt_lo);
    cudaGetSymbolAddress((void**)&psWth,   g_sWt_hi);
    cudaGetSymbolAddress((void**)&psWtl,   g_sWt_lo);

    cudaFuncSetAttribute(lstm_scan_w, cudaFuncAttributeMaxDynamicSharedMemorySize,
                         2*8*1024*4 + 256*8*4);
    cudaFuncSetAttribute(lstm_scan_s, cudaFuncAttributeMaxDynamicSharedMemorySize,
                         2*8*1024*4 + 256*4);
    cudaFuncSetAttribute(gemm_wb, cudaFuncAttributeMaxDynamicSharedMemorySize,
                         GEMM_SMEM2);

    // 1. gather + padding
    gather_x_kernel<<<(M1*DIN1 + 255)/256, 256>>>(tok, wpos, emb, wpe);
    pad_x_kernel<<<(M1*(XKP-DIN1) + 255)/256, 256>>>();
    pad_z_kernel<<<(M1*(ZKP-DATT) + 255)/256, 256>>>();

    // 2. weight conversions + Whh transposes
    conv_pad<<<(Gn*XKP + 255)/256, 256>>>(wWih_f, pwihfh, pwihfl, Gn, DIN1, XKP);
    conv_pad<<<(Gn*XKP + 255)/256, 256>>>(wWih_b, pwihbh, pwihbl, Gn, DIN1, XKP);
    conv_pad<<<(Gn*ZKP + 255)/256, 256>>>(sWih_f, psihfh, psihfl, Gn, DATT, ZKP);
    conv_pad<<<(Gn*ZKP + 255)/256, 256>>>(sWih_b, psihbh, psihbl, Gn, DATT, ZKP);
    conv_wt<<<(ZKP*ZKP + 255)/256, 256>>>(word_W, pwWth, pwWtl, DATT, ZKP, ZKP);
    conv_wt<<<(ZKP*ZKP + 255)/256, 256>>>(sent_W, psWth, psWtl, DATT, ZKP, ZKP);
    transpose_k<<<(Gn*Hn + 255)/256, 256>>>(wWhh_f, pwtf, Gn, Hn);
    transpose_k<<<(Gn*Hn + 255)/256, 256>>>(wWhh_b, pwtb, Gn, Hn);
    transpose_k<<<(Gn*Hn + 255)/256, 256>>>(sWhh_f, pstf, Gn, Hn);
    transpose_k<<<(Gn*Hn + 255)/256, 256>>>(sWhh_b, pstb, Gn, Hn);

    // 3. word input GEMMs (bias in accumulators, direct store)
    {
        dim3 g(Gn/128, M1/128);
        rep_bias<<<(16*Gn + 255)/256, 256>>>(wb_f, Gn);
        gemm_wb<<<g, 256, GEMM_SMEM2>>>(pxhi, pxlo, pwihfh, pwihfl, pbrep,
                                        (const float*)0, (const float*)0,
                                        pgpre, M1, Gn, XKP, Gn, 0);
        rep_bias<<<(16*Gn + 255)/256, 256>>>(wb_b, Gn);
        gemm_wb<<<g, 256, GEMM_SMEM2>>>(pxhi, pxlo, pwihbh, pwihbl, pbrep,
                                        (const float*)0, (const float*)0,
                                        pgpre + (size_t)M1*Gn, M1, Gn, XKP, Gn, 0);
    }

    // 4. word BiLSTM scan -> d_z fp32 + z bf16
    lstm_scan_w<<<128, 256, 2*8*1024*4 + 256*8*4>>>(pgpre, pwtf, pwtb, pz,
                                                    pzhi, pzlo, N1, Ln, DATT);

    // 5. word attention
    gemm_wb<<<dim3(NBATT, M1/128), 256, GEMM_SMEM2>>>(pzhi, pzlo, pwWth, pwWtl,
                                                      (const float*)0, word_b, word_p,
                                                      pscp, M1, ZKP, ZKP, DATT, 1);
    sum_scores<<<(M1 + 255)/256, 256>>>(pscp, psc, M1, NBATT);
    softmax_pool_kernel<<<N1, 256>>>(psc, pz, psenvec, Ln, DATT);

    // 6. sentence input
    build_sx_kernel<<<(N1*ZKP + 255)/256, 256>>>(seg, spe);
    fill_z2pos<<<(N1*(ZKP-2*Hn) + 255)/256, 256>>>(seg, spe);
    {
        dim3 g(Gn/128, N1/128);
        rep_bias<<<(16*Gn + 255)/256, 256>>>(sb_f, Gn);
        gemm_wb<<<g, 256, GEMM_SMEM2>>>(psxhi, psxlo, psihfh, psihfl, pbrep,
                                        (const float*)0, (const float*)0,
                                        pgpre2, N1, Gn, ZKP, Gn, 0);
        rep_bias<<<(16*Gn + 255)/256, 256>>>(sb_b, Gn);
        gemm_wb<<<g, 256, GEMM_SMEM2>>>(psxhi, psxlo, psihbh, psihbl, pbrep,
                                        (const float*)0, (const float*)0,
                                        pgpre2 + (size_t)N1*Gn, N1, Gn, ZKP, Gn, 0);
    }

    // 7. sentence BiLSTM scan -> d_z2 fp32 + z2 bf16, keeps hT
    lstm_scan_s<<<2*Bn, 256, 2*8*1024*4 + 256*4>>>(pgpre2, pstf, pstb, pz2,
                                                   pz2hi, pz2lo, phT, Bn, Sn, DATT);

    // 8. sentence attention
    gemm_wb<<<dim3(NBATT, N1/128), 256, GEMM_SMEM2>>>(pz2hi, pz2lo, psWth, psWtl,
                                                      (const float*)0, sent_b, sent_p,
                                                      pscp2, N1, ZKP, ZKP, DATT, 1);
    sum_scores<<<(N1 + 255)/256, 256>>>(pscp2, psc2, N1, NBATT);
    softmax_pool_kernel<<<Bn, 256>>>(psc2, pz2, pdocvec, Sn, DATT);

    // 9. classifier head
    final_dense_kernel<<<Bn, 128>>>(dense_W, dense_b, outp);
}

// round 15
// speedup vs baseline: 1.3967x; 1.2298x over previous
#include <cuda_runtime.h>
#include <cuda_fp16.h>
#include <mma.h>
#include <cstdint>
#include <math.h>

using namespace nvcuda;

// ---------------- problem constants ----------------
#define Bn   32
#define Sn   16
#define Ln   64
#define En   300
#define Pn   100
#define Hn   256
#define Gn   1024
#define DATT 612
#define N1   (Bn*Sn)
#define M1   (N1*Ln)
#define DIN1 (En+Pn)
#define NBATT 5             // 640/128
#define XKP  416            // padded K for x (400)
#define ZKP  640            // padded K/N for 612

typedef unsigned long long u64;

// ---------------- scratch (device globals) ----------------------------------
__device__ float d_gpre[2*M1*Gn];
__device__ float d_z[M1*DATT];
__device__ float d_scp[M1*NBATT];
__device__ float d_scores[M1];
__device__ float d_senvec[N1*2*Hn];
__device__ float d_gpre2[2*N1*Gn];
__device__ float d_z2[N1*DATT];
__device__ float d_hT[2*Bn*Hn];
__device__ float d_scp2[N1*NBATT];
__device__ float d_scores2[N1];
__device__ float d_docvec[Bn*2*Hn];
__device__ float d_wtf[Hn*Gn];
__device__ float d_wtb[Hn*Gn];
__device__ float d_stf[Hn*Gn];
__device__ float d_stb[Hn*Gn];
__device__ float d_brep[16*Gn];     // replicated bias (16 identical rows)
__device__ __half g_x[M1*XKP];
__device__ __half g_zb[(size_t)M1*ZKP];
__device__ __half g_sx[N1*ZKP];
__device__ __half g_z2b[N1*ZKP];
__device__ __half g_wihf[Gn*XKP];
__device__ __half g_wihb[Gn*XKP];
__device__ __half g_sihf[Gn*ZKP];
__device__ __half g_sihb[Gn*ZKP];
__device__ __half g_wWt[ZKP*ZKP];
__device__ __half g_sWt[ZKP*ZKP];

__device__ __forceinline__ float sigmoidf(float x) { return 1.0f / (1.0f + expf(-x)); }

__device__ __forceinline__ void fma2(u64& d, u64 a, u64 b) {
    asm("fma.rn.f32x2 %0, %1, %2, %3;" : "=l"(d) : "l"(a), "l"(b), "l"(d));
}
__device__ __forceinline__ u64 pack2(float x, float y) {
    u64 r; asm("mov.b64 %0, {%1,%2};" : "=l"(r) : "f"(x), "f"(y)); return r;
}
__device__ __forceinline__ void unpack2(float& lo, float& hi, u64 v) {
    asm("mov.b64 {%0,%1}, %2;" : "=f"(lo), "=f"(hi) : "l"(v));
}
__device__ __forceinline__ uint32_t smem_u32(const void* p) {
    return (uint32_t)__cvta_generic_to_shared(p);
}
__device__ __forceinline__ void cp16(uint32_t dst, const void* src) {
    asm volatile("cp.async.cg.shared.global [%0], [%1], 16;" :: "r"(dst), "l"(src));
}
#define CP_COMMIT() asm volatile("cp.async.commit_group;" ::: "memory")
#define CP_WAIT0()  asm volatile("cp.async.wait_group 0;" ::: "memory")

// ======================= WMMA fp16 GEMM, 128x128 tile ========================
// C[M,Nc] = A[M,KP] @ B[*,KP]^T, fp16 operands, fp32 accumulate, KP mult 32,
// M mult 128, Nc mult 128. cp.async double buffer, K-step 32.
// Tiles padded to 40-elem (80B) rows -> conflict-free LDSM. 2 CTAs/SM.
// attn==0: accumulators init from d_brep (bias, ldm Gn) -> direct global store.
// attn!=0: smem out tile + tanh/proj row-reduction ->
//          C[m*gridDim.x + bx] = sum_{n<Nv} tanh(acc+bias[n])*proj[n]
// smem: 2 stages x (A 128x40 + B 128x40 fp16, 10240B each) = 40960B;
// attn epilogue reuses [0,65536) as 128x128 f32 out tile; red at +65536.
#define TSEH  5120            // tile stride, halves
#define SSEH  10240           // stage stride, halves
#define GEMM_SMEM2 66560

__global__ __launch_bounds__(256, 2)
void gemm_h(const __half* __restrict__ A, const __half* __restrict__ B,
            const float* __restrict__ brep, const float* __restrict__ bias,
            const float* __restrict__ proj,
            float* __restrict__ C, int M, int Nc, int KP, int Nv, int attn)
{
    extern __shared__ float dynsm[];
    __half* sb  = (__half*)dynsm;    // staged tiles
    float* outs = dynsm;             // reused after mainloop (attn path)
    float* red  = dynsm + 16384;     // byte 65536

    const int tid = threadIdx.x;
    const int m0 = blockIdx.y * 128;
    const int n0 = blockIdx.x * 128;
    const int w  = tid >> 5;
    const int wm = w >> 1;           // 0..3  (32-row band)
    const int wn = w & 1;            // 0..1  (64-col band)

    wmma::fragment<wmma::accumulator, 16, 16, 16, float> acc[2][4];
    if (attn == 0) {
#pragma unroll
        for (int i = 0; i < 2; i++)
#pragma unroll
            for (int j = 0; j < 4; j++)
                wmma::load_matrix_sync(acc[i][j], brep + n0 + wn*64 + j*16, Gn,
                                       wmma::mem_row_major);
    } else {
#pragma unroll
        for (int i = 0; i < 2; i++)
#pragma unroll
            for (int j = 0; j < 4; j++)
                wmma::fill_fragment(acc[i][j], 0.0f);
    }

    const int nk   = KP / 32;
    const int rowi = tid >> 1;               // 0..127
    const int kof  = (tid & 1) * 16;         // halves
    const uint32_t sbase = smem_u32(sb);
    const uint32_t boff  = (uint32_t)(rowi * 80 + kof * 2);   // bytes in tile

    const __half* __restrict__ pa = A + (size_t)(m0 + rowi) * KP + kof;
    const __half* __restrict__ pb = B + (size_t)(n0 + rowi) * KP + kof;

    // stage chunk 0 into buffer 0 (A @ +0, B @ +10240B; stage stride 20480B)
    {
        const uint32_t d0 = sbase + boff;
        cp16(d0 +     0, pa);     cp16(d0 +    16, pa + 8);
        cp16(d0 + 10240, pb);     cp16(d0 + 10240 + 16, pb + 8);
        CP_COMMIT();
        CP_WAIT0();
    }
    __syncthreads();

    for (int kc = 0; kc < nk; kc++) {
        const int cur = kc & 1;
        if (kc + 1 < nk) {
            const int go = (kc + 1) * 32;
            const uint32_t d1 = sbase + (uint32_t)((cur ^ 1) * 20480) + boff;
            cp16(d1 +     0, pa + go);     cp16(d1 +    16, pa + go + 8);
            cp16(d1 + 10240, pb + go);     cp16(d1 + 10240 + 16, pb + go + 8);
            CP_COMMIT();
        }
        const __half* Ah = sb + cur * SSEH;
        const __half* Bh = Ah + TSEH;
#pragma unroll
        for (int kf = 0; kf < 2; kf++) {
            wmma::fragment<wmma::matrix_a, 16, 16, 16, __half, wmma::row_major> ah[2];
#pragma unroll
            for (int i = 0; i < 2; i++) {
                wmma::load_matrix_sync(ah[i], Ah + (wm*32 + i*16)*40 + kf*16, 40);
            }
#pragma unroll
            for (int j = 0; j < 4; j++) {
                wmma::fragment<wmma::matrix_b, 16, 16, 16, __half, wmma::col_major> bh;
                wmma::load_matrix_sync(bh, Bh + (wn*64 + j*16)*40 + kf*16, 40);
#pragma unroll
                for (int i = 0; i < 2; i++) {
                    wmma::mma_sync(acc[i][j], ah[i], bh, acc[i][j]);
                }
            }
        }
        if (kc + 1 < nk) CP_WAIT0();
        __syncthreads();
    }

    if (attn == 0) {
        // direct global store (bias already in accumulators)
#pragma unroll
        for (int i = 0; i < 2; i++)
#pragma unroll
            for (int j = 0; j < 4; j++)
                wmma::store_matrix_sync(
                    C + (size_t)(m0 + wm*32 + i*16) * Nc + n0 + wn*64 + j*16,
                    acc[i][j], Nc, wmma::mem_row_major);
    } else {
        // epilogue: reuse smem as fp32 out tile [128][128]
#pragma unroll
        for (int i = 0; i < 2; i++)
#pragma unroll
            for (int j = 0; j < 4; j++)
                wmma::store_matrix_sync(outs + (size_t)(wm*32 + i*16)*128 + wn*64 + j*16,
                                        acc[i][j], 128, wmma::mem_row_major);
        __syncthreads();
        const int row = tid >> 1;
        const int hf  = (tid & 1) * 64;
        float part = 0.f;
#pragma unroll
        for (int c = 0; c < 64; c++) {
            int n = n0 + hf + c;
            if (n < Nv) part += tanhf(outs[row*128 + hf + c] + bias[n]) * proj[n];
        }
        red[tid] = part;
        __syncthreads();
        if (tid < 128) {
            C[(size_t)(m0 + tid) * gridDim.x + blockIdx.x] = red[2*tid] + red[2*tid + 1];
        }
    }
}

// ---------------- bias replication (16 identical rows) ------------------------
__global__ void rep_bias(const float* __restrict__ bias, int Nc)
{
    int idx = blockIdx.x * blockDim.x + threadIdx.x;
    if (idx >= 16 * Nc) return;
    d_brep[(idx / Nc) * Gn + (idx % Nc)] = bias[idx % Nc];
}

// ---------------- gather: x fp16 + z pos cols fp16 ----------------------------
__global__ void gather_x_kernel(const int* __restrict__ tok,
                                const int* __restrict__ wpos,
                                const float* __restrict__ emb,
                                const float* __restrict__ wpe)
{
    int idx = blockIdx.x * blockDim.x + threadIdx.x;
    if (idx >= M1 * DIN1) return;
    int d = idx % DIN1;
    int m = idx / DIN1;
    float v;
    if (d < En) {
        v = emb[(size_t)tok[m] * En + d];
    } else {
        v = wpe[(size_t)wpos[m] * Pn + (d - En)];
        g_zb[(size_t)m * ZKP + 2*Hn + (d - En)] = __float2half(v);
    }
    g_x[(size_t)m * XKP + d] = __float2half(v);
}

__global__ void pad_x_kernel()
{
    int idx = blockIdx.x * blockDim.x + threadIdx.x;
    if (idx >= M1 * (XKP - DIN1)) return;
    int m = idx / (XKP - DIN1);
    int k = DIN1 + idx % (XKP - DIN1);
    g_x[(size_t)m * XKP + k] = __float2half(0.f);
}

__global__ void pad_z_kernel()
{
    int idx = blockIdx.x * blockDim.x + threadIdx.x;
    if (idx >= M1 * (ZKP - DATT)) return;
    int m = idx / (ZKP - DATT);
    int k = DATT + idx % (ZKP - DATT);
    g_zb[(size_t)m * ZKP + k] = __float2half(0.f);
}

// ---------------- weight conversions -------------------------------------------
__global__ void conv_pad(const float* __restrict__ W, __half* __restrict__ out,
                         int rows, int kc, int kp)
{
    int idx = blockIdx.x * blockDim.x + threadIdx.x;
    if (idx >= rows * kp) return;
    int r = idx / kp;
    int k = idx % kp;
    float v = (k < kc) ? W[(size_t)r * kc + k] : 0.f;
    out[idx] = __float2half(v);
}

__global__ void conv_wt(const float* __restrict__ W, __half* __restrict__ out,
                        int d, int np, int kp)
{
    int idx = blockIdx.x * blockDim.x + threadIdx.x;
    if (idx >= np * kp) return;
    int e = idx / kp;
    int k = idx % kp;
    float v = (e < d && k < d) ? W[(size_t)k * d + e] : 0.f;
    out[idx] = __float2half(v);
}

// ---------------- transpose (Whh for scans) -------------------------------------
__global__ void transpose_k(const float* __restrict__ W, float* __restrict__ Wt,
                            int Gr, int Kc)
{
    int idx = blockIdx.x * blockDim.x + threadIdx.x;
    if (idx >= Gr * Kc) return;
    int g = idx / Kc;
    int k = idx % Kc;
    Wt[(size_t)k * Gr + g] = W[idx];
}

// ---------------- word BiLSTM scan (8 rows/block) ------------------------------
__global__ __launch_bounds__(256, 1)
void lstm_scan_w(const float* __restrict__ gpre,
                 const float* __restrict__ Wt_f,
                 const float* __restrict__ Wt_b,
                 float* __restrict__ out,
                 __half* __restrict__ zh,
                 int N, int T, int ostride)
{
    extern __shared__ float dynsm[];
    float* ws = dynsm;
    float* hs = dynsm + 2*8*1024;
    const int tid = threadIdx.x;
    const int nb  = N / 8;
    const int dir = blockIdx.x / nb;
    const int n0  = (blockIdx.x % nb) * 8;
    const float* __restrict__ Wt = dir ? Wt_b : Wt_f;

    float c[8];
#pragma unroll
    for (int r = 0; r < 8; r++) c[r] = 0.f;
    for (int i = tid; i < 256*8; i += 256) hs[i] = 0.f;

#pragma unroll
    for (int i = 0; i < 8; i++) {
        *(float4*)&ws[(tid + 256*i)*4] = *(const float4*)&Wt[(tid + 256*i)*4];
    }
    __syncthreads();

    const int NT = 32;
    for (int step = 0; step < T; step++) {
        const int tt = dir ? (T - 1 - step) : step;
        u64 acc2[4][4];
#pragma unroll
        for (int rp = 0; rp < 4; rp++) {
            size_t b0 = ((size_t)(dir*N + n0 + rp*2    ) * T + tt) * Gn;
            size_t b1 = ((size_t)(dir*N + n0 + rp*2 + 1) * T + tt) * Gn;
#pragma unroll
            for (int g = 0; g < 4; g++) {
                acc2[rp][g] = pack2(gpre[b0 + g*256 + tid], gpre[b1 + g*256 + tid]);
            }
        }
        for (int kt = 0; kt < NT; kt++) {
            const int cur = kt & 1;
            const bool last = (step == T-1) && (kt == NT-1);
            float4 pf[8];
            if (!last) {
                const float* src = &Wt[(size_t)((kt + 1) & 31) * 8192];
#pragma unroll
                for (int i = 0; i < 8; i++) {
                    pf[i] = *(const float4*)&src[(tid + 256*i)*4];
                }
            }
#pragma unroll
            for (int kk = 0; kk < 8; kk++) {
                const int k = kt*8 + kk;
                const float* wrow = &ws[(cur*8 + kk)*1024];
                float w0 = wrow[tid];
                float w1 = wrow[256+tid];
                float w2 = wrow[512+tid];
                float w3 = wrow[768+tid];
                u64 wd0 = pack2(w0,w0);
                u64 wd1 = pack2(w1,w1);
                u64 wd2 = pack2(w2,w2);
                u64 wd3 = pack2(w3,w3);
#pragma unroll
                for (int rp = 0; rp < 4; rp++) {
                    u64 h2 = *(const u64*)&hs[k*8 + rp*2];
                    fma2(acc2[rp][0], h2, wd0);
                    fma2(acc2[rp][1], h2, wd1);
                    fma2(acc2[rp][2], h2, wd2);
                    fma2(acc2[rp][3], h2, wd3);
                }
            }
            if (!last) {
                float* dst = &ws[(cur ^ 1) * 8192];
#pragma unroll
                for (int i = 0; i < 8; i++) {
                    *(float4*)&dst[(tid + 256*i)*4] = pf[i];
                }
            }
            __syncthreads();
        }
#pragma unroll
        for (int rp = 0; rp < 4; rp++) {
            float p0[2];
            float p1[2];
            float p2[2];
            float p3[2];
            unpack2(p0[0], p0[1], acc2[rp][0]);
            unpack2(p1[0], p1[1], acc2[rp][1]);
            unpack2(p2[0], p2[1], acc2[rp][2]);
            unpack2(p3[0], p3[1], acc2[rp][3]);
#pragma unroll
            for (int hh = 0; hh < 2; hh++) {
                int r = rp*2 + hh;
                float iv = sigmoidf(p0[hh]);
                float fv = sigmoidf(p1[hh]);
                float gv = tanhf(p2[hh]);
                float ov = sigmoidf(p3[hh]);
                c[r] = fv * c[r] + iv * gv;
                float hv = ov * tanhf(c[r]);
                hs[tid*8 + r] = hv;
                size_t mrow = (size_t)(n0 + r) * T + tt;
                out[mrow * ostride + dir*256 + tid] = hv;
                zh[mrow * ZKP + dir*256 + tid] = __float2half(hv);
            }
        }
        __syncthreads();
    }
}

// ---------------- sentence BiLSTM scan (1 row/block, keeps hT) ------------------
__global__ __launch_bounds__(256, 1)
void lstm_scan_s(const float* __restrict__ gpre,
                 const float* __restrict__ Wt_f,
                 const float* __restrict__ Wt_b,
                 float* __restrict__ out,
                 __half* __restrict__ zh,
                 float* __restrict__ hT,
                 int N, int T, int ostride)
{
    extern __shared__ float dynsm[];
    float* ws = dynsm;
    float* hs = dynsm + 2*8*1024;
    const int tid = threadIdx.x;
    const int dir = blockIdx.x / N;
    const int n0  = blockIdx.x % N;
    const float* __restrict__ Wt = dir ? Wt_b : Wt_f;

    float c0 = 0.f;
    hs[tid] = 0.f;

#pragma unroll
    for (int i = 0; i < 8; i++) {
        *(float4*)&ws[(tid + 256*i)*4] = *(const float4*)&Wt[(tid + 256*i)*4];
    }
    __syncthreads();

    const int NT = 32;
    for (int step = 0; step < T; step++) {
        const int tt = dir ? (T - 1 - step) : step;
        float acc[4];
        size_t b0 = ((size_t)(dir*N + n0) * T + tt) * Gn;
#pragma unroll
        for (int g = 0; g < 4; g++) {
            acc[g] = gpre[b0 + g*256 + tid];
        }
        for (int kt = 0; kt < NT; kt++) {
            const int cur = kt & 1;
            const bool last = (step == T-1) && (kt == NT-1);
            float4 pf[8];
            if (!last) {
                const float* src = &Wt[(size_t)((kt + 1) & 31) * 8192];
#pragma unroll
                for (int i = 0; i < 8; i++) {
                    pf[i] = *(const float4*)&src[(tid + 256*i)*4];
                }
            }
#pragma unroll
            for (int kk = 0; kk < 8; kk++) {
                const int k = kt*8 + kk;
                const float* wrow = &ws[(cur*8 + kk)*1024];
                float hv = hs[k];
                acc[0] += hv * wrow[tid];
                acc[1] += hv * wrow[256+tid];
                acc[2] += hv * wrow[512+tid];
                acc[3] += hv * wrow[768+tid];
            }
            if (!last) {
                float* dst = &ws[(cur ^ 1) * 8192];
#pragma unroll
                for (int i = 0; i < 8; i++) {
                    *(float4*)&dst[(tid + 256*i)*4] = pf[i];
                }
            }
            __syncthreads();
        }
        float iv = sigmoidf(acc[0]);
        float fv = sigmoidf(acc[1]);
        float gv = tanhf(acc[2]);
        float ov = sigmoidf(acc[3]);
        c0 = fv * c0 + iv * gv;
        float hv = ov * tanhf(c0);
        hs[tid] = hv;
        size_t mrow = (size_t)n0 * T + tt;
        out[mrow * ostride + dir*256 + tid] = hv;
        zh[mrow * ZKP + dir*256 + tid] = __float2half(hv);
        if (step == T - 1) {
            hT[((size_t)dir * N + n0) * 256 + tid] = hv;
        }
        __syncthreads();
    }
}

// ---------------- attention glue -----------------------------------------------
__global__ void sum_scores(const float* __restrict__ scp, float* __restrict__ sc,
                           int M, int NB)
{
    int m = blockIdx.x * blockDim.x + threadIdx.x;
    if (m >= M) return;
    float s = 0.f;
    for (int j = 0; j < NB; j++) s += scp[(size_t)m * NB + j];
    sc[m] = s;
}

__global__ void softmax_pool_kernel(const float* __restrict__ sc,
                                    const float* __restrict__ hsrc,
                                    float* __restrict__ outv,
                                    int T, int stride)
{
    __shared__ float a[64];
    __shared__ float inv_s;
    int n = blockIdx.x;
    int tid = threadIdx.x;
    if (tid == 0) {
        float mx = -1e30f;
        for (int t = 0; t < T; t++) mx = fmaxf(mx, sc[n * T + t]);
        float sum = 0.f;
        for (int t = 0; t < T; t++) {
            float e = expf(sc[n * T + t] - mx);
            a[t] = e;
            sum += e;
        }
        inv_s = 1.f / sum;
    }
    __syncthreads();
    float inv = inv_s;
    for (int col = tid; col < 2*Hn; col += blockDim.x) {
        float acc = 0.f;
        for (int t = 0; t < T; t++) {
            acc += a[t] * hsrc[((size_t)n * T + t) * stride + col];
        }
        outv[(size_t)n * (2*Hn) + col] = acc * inv;
    }
}

__global__ void build_sx_kernel(const int* __restrict__ seg,
                                const float* __restrict__ spe)
{
    int idx = blockIdx.x * blockDim.x + threadIdx.x;
    if (idx >= N1 * ZKP) return;
    int d = idx % ZKP;
    int m = idx / ZKP;
    float v;
    if (d < 2*Hn)      v = d_senvec[(size_t)m * (2*Hn) + d];
    else if (d < DATT) v = spe[(size_t)seg[m] * Pn + (d - 2*Hn)];
    else               v = 0.f;
    g_sx[idx] = __float2half(v);
}

__global__ void fill_z2pos(const int* __restrict__ seg, const float* __restrict__ spe)
{
    int idx = blockIdx.x * blockDim.x + threadIdx.x;
    if (idx >= N1 * (ZKP - 2*Hn)) return;
    int m = idx / (ZKP - 2*Hn);
    int d = idx % (ZKP - 2*Hn);
    float v = (d < Pn) ? spe[(size_t)seg[m] * Pn + d] : 0.f;
    g_z2b[(size_t)m * ZKP + 2*Hn + d] = __float2half(v);
}

// ---------------- classifier head ------------------------------------------------
__global__ void final_dense_kernel(const float* __restrict__ dW,
                                   const float* __restrict__ db,
                                   float* __restrict__ outp)
{
    __shared__ float r0[128];
    __shared__ float r1[128];
    __shared__ float r2[128];
    int b = blockIdx.x;
    int tid = threadIdx.x;
    float a0 = 0.f, a1 = 0.f, a2 = 0.f;
    for (int k = tid; k < 4*Hn; k += 128) {
        float f;
        if (k < 2*Hn)      f = d_docvec[b * 2*Hn + k];
        else if (k < 3*Hn) f = d_hT[(0 * Bn + b) * Hn + (k - 2*Hn)];
        else               f = d_hT[(1 * Bn + b) * Hn + (k - 3*Hn)];
        a0 += f * dW[0*4*Hn + k];
        a1 += f * dW[1*4*Hn + k];
        a2 += f * dW[2*4*Hn + k];
    }
    r0[tid] = a0;
    r1[tid] = a1;
    r2[tid] = a2;
    __syncthreads();
    for (int s = 64; s > 0; s >>= 1) {
        if (tid < s) {
            r0[tid] += r0[tid+s];
            r1[tid] += r1[tid+s];
            r2[tid] += r2[tid+s];
        }
        __syncthreads();
    }
    if (tid == 0) {
        outp[b*3+0] = r0[0] + db[0];
        outp[b*3+1] = r1[0] + db[1];
        outp[b*3+2] = r2[0] + db[2];
    }
}

// ---------------- host driver ------------------------------------------------------
extern "C" void kernel_launch(void* const* d_in, const int* in_sizes, int n_in,
                              void* d_out, int out_size)
{
    const int*   tok     = (const int*)d_in[0];
    const int*   wpos    = (const int*)d_in[1];
    const int*   seg     = (const int*)d_in[2];
    const float* emb     = (const float*)d_in[3];
    const float* wpe     = (const float*)d_in[4];
    const float* spe     = (const float*)d_in[5];
    const float* wWih_f  = (const float*)d_in[6];
    const float* wWhh_f  = (const float*)d_in[7];
    const float* wb_f    = (const float*)d_in[8];
    const float* wWih_b  = (const float*)d_in[9];
    const float* wWhh_b  = (const float*)d_in[10];
    const float* wb_b    = (const float*)d_in[11];
    const float* sWih_f  = (const float*)d_in[12];
    const float* sWhh_f  = (const float*)d_in[13];
    const float* sb_f    = (const float*)d_in[14];
    const float* sWih_b  = (const float*)d_in[15];
    const float* sWhh_b  = (const float*)d_in[16];
    const float* sb_b    = (const float*)d_in[17];
    const float* word_W  = (const float*)d_in[18];
    const float* word_b  = (const float*)d_in[19];
    const float* word_p  = (const float*)d_in[20];
    const float* sent_W  = (const float*)d_in[21];
    const float* sent_b  = (const float*)d_in[22];
    const float* sent_p  = (const float*)d_in[23];
    const float* dense_W = (const float*)d_in[24];
    const float* dense_b = (const float*)d_in[25];
    float* outp = (float*)d_out;

    float *pgpre, *pz, *pscp, *psc, *psenvec, *pgpre2, *pz2,
          *phT, *pscp2, *psc2, *pdocvec, *pwtf, *pwtb, *pstf, *pstb, *pbrep;
    __half *px, *pzb, *psx, *pz2b, *pwihf, *pwihb, *psihf, *psihb, *pwWt, *psWt;
    cudaGetSymbolAddress((void**)&pgpre,   d_gpre);
    cudaGetSymbolAddress((void**)&pz,      d_z);
    cudaGetSymbolAddress((void**)&pscp,    d_scp);
    cudaGetSymbolAddress((void**)&psc,     d_scores);
    cudaGetSymbolAddress((void**)&psenvec, d_senvec);
    cudaGetSymbolAddress((void**)&pgpre2,  d_gpre2);
    cudaGetSymbolAddress((void**)&pz2,     d_z2);
    cudaGetSymbolAddress((void**)&phT,     d_hT);
    cudaGetSymbolAddress((void**)&pscp2,   d_scp2);
    cudaGetSymbolAddress((void**)&psc2,    d_scores2);
    cudaGetSymbolAddress((void**)&pdocvec, d_docvec);
    cudaGetSymbolAddress((void**)&pwtf,    d_wtf);
    cudaGetSymbolAddress((void**)&pwtb,    d_wtb);
    cudaGetSymbolAddress((void**)&pstf,    d_stf);
    cudaGetSymbolAddress((void**)&pstb,    d_stb);
    cudaGetSymbolAddress((void**)&pbrep,   d_brep);
    cudaGetSymbolAddress((void**)&px,      g_x);
    cudaGetSymbolAddress((void**)&pzb,     g_zb);
    cudaGetSymbolAddress((void**)&psx,     g_sx);
    cudaGetSymbolAddress((void**)&pz2b,    g_z2b);
    cudaGetSymbolAddress((void**)&pwihf,   g_wihf);
    cudaGetSymbolAddress((void**)&pwihb,   g_wihb);
    cudaGetSymbolAddress((void**)&psihf,   g_sihf);
    cudaGetSymbolAddress((void**)&psihb,   g_sihb);
    cudaGetSymbolAddress((void**)&pwWt,    g_wWt);
    cudaGetSymbolAddress((void**)&psWt,    g_sWt);

    cudaFuncSetAttribute(lstm_scan_w, cudaFuncAttributeMaxDynamicSharedMemorySize,
                         2*8*1024*4 + 256*8*4);
    cudaFuncSetAttribute(lstm_scan_s, cudaFuncAttributeMaxDynamicSharedMemorySize,
                         2*8*1024*4 + 256*4);
    cudaFuncSetAttribute(gemm_h, cudaFuncAttributeMaxDynamicSharedMemorySize,
                         GEMM_SMEM2);

    // 1. gather + padding
    gather_x_kernel<<<(M1*DIN1 + 255)/256, 256>>>(tok, wpos, emb, wpe);
    pad_x_kernel<<<(M1*(XKP-DIN1) + 255)/256, 256>>>();
    pad_z_kernel<<<(M1*(ZKP-DATT) + 255)/256, 256>>>();

    // 2. weight conversions + Whh transposes
    conv_pad<<<(Gn*XKP + 255)/256, 256>>>(wWih_f, pwihf, Gn, DIN1, XKP);
    conv_pad<<<(Gn*XKP + 255)/256, 256>>>(wWih_b, pwihb, Gn, DIN1, XKP);
    conv_pad<<<(Gn*ZKP + 255)/256, 256>>>(sWih_f, psihf, Gn, DATT, ZKP);
    conv_pad<<<(Gn*ZKP + 255)/256, 256>>>(sWih_b, psihb, Gn, DATT, ZKP);
    conv_wt<<<(ZKP*ZKP + 255)/256, 256>>>(word_W, pwWt, DATT, ZKP, ZKP);
    conv_wt<<<(ZKP*ZKP + 255)/256, 256>>>(sent_W, psWt, DATT, ZKP, ZKP);
    transpose_k<<<(Gn*Hn + 255)/256, 256>>>(wWhh_f, pwtf, Gn, Hn);
    transpose_k<<<(Gn*Hn + 255)/256, 256>>>(wWhh_b, pwtb, Gn, Hn);
    transpose_k<<<(Gn*Hn + 255)/256, 256>>>(sWhh_f, pstf, Gn, Hn);
    transpose_k<<<(Gn*Hn + 255)/256, 256>>>(sWhh_b, pstb, Gn, Hn);

    // 3. word input GEMMs (fp16 operands, bias in accumulators, direct store)
    {
        dim3 g(Gn/128, M1/128);
        rep_bias<<<(16*Gn + 255)/256, 256>>>(wb_f, Gn);
        gemm_h<<<g, 256, GEMM_SMEM2>>>(px, pwihf, pbrep, (const float*)0,
                                       (const float*)0, pgpre, M1, Gn, XKP, Gn, 0);
        rep_bias<<<(16*Gn + 255)/256, 256>>>(wb_b, Gn);
        gemm_h<<<g, 256, GEMM_SMEM2>>>(px, pwihb, pbrep, (const float*)0,
                                       (const float*)0,
                                       pgpre + (size_t)M1*Gn, M1, Gn, XKP, Gn, 0);
    }

    // 4. word BiLSTM scan -> d_z fp32 + z fp16
    lstm_scan_w<<<128, 256, 2*8*1024*4 + 256*8*4>>>(pgpre, pwtf, pwtb, pz,
                                                    pzb, N1, Ln, DATT);

    // 5. word attention
    gemm_h<<<dim3(NBATT, M1/128), 256, GEMM_SMEM2>>>(pzb, pwWt, (const float*)0,
                                                     word_b, word_p,
                                                     pscp, M1, ZKP, ZKP, DATT, 1);
    sum_scores<<<(M1 + 255)/256, 256>>>(pscp, psc, M1, NBATT);
    softmax_pool_kernel<<<N1, 256>>>(psc, pz, psenvec, Ln, DATT);

    // 6. sentence input
    build_sx_kernel<<<(N1*ZKP + 255)/256, 256>>>(seg, spe);
    fill_z2pos<<<(N1*(ZKP-2*Hn) + 255)/256, 256>>>(seg, spe);
    {
        dim3 g(Gn/128, N1/128);
        rep_bias<<<(16*Gn + 255)/256, 256>>>(sb_f, Gn);
        gemm_h<<<g, 256, GEMM_SMEM2>>>(psx, psihf, pbrep, (const float*)0,
                                       (const float*)0, pgpre2, N1, Gn, ZKP, Gn, 0);
        rep_bias<<<(16*Gn + 255)/256, 256>>>(sb_b, Gn);
        gemm_h<<<g, 256, GEMM_SMEM2>>>(psx, psihb, pbrep, (const float*)0,
                                       (const float*)0,
                                       pgpre2 + (size_t)N1*Gn, N1, Gn, ZKP, Gn, 0);
    }

    // 7. sentence BiLSTM scan -> d_z2 fp32 + z2 fp16, keeps hT
    lstm_scan_s<<<2*Bn, 256, 2*8*1024*4 + 256*4>>>(pgpre2, pstf, pstb, pz2,
                                                   pz2b, phT, Bn, Sn, DATT);

    // 8. sentence attention
    gemm_h<<<dim3(NBATT, N1/128), 256, GEMM_SMEM2>>>(pz2b, psWt, (const float*)0,
                                                     sent_b, sent_p,
                                                     pscp2, N1, ZKP, ZKP, DATT, 1);
    sum_scores<<<(N1 + 255)/256, 256>>>(pscp2, psc2, N1, NBATT);
    softmax_pool_kernel<<<Bn, 256>>>(psc2, pz2, pdocvec, Sn, DATT);

    // 9. classifier head
    final_dense_kernel<<<Bn, 128>>>(dense_W, dense_b, outp);
}

// round 16
// speedup vs baseline: 1.7242x; 1.2345x over previous
#include <cuda_runtime.h>
#include <cuda_fp16.h>
#include <mma.h>
#include <cstdint>
#include <math.h>

using namespace nvcuda;

// ---------------- problem constants ----------------
#define Bn   32
#define Sn   16
#define Ln   64
#define En   300
#define Pn   100
#define Hn   256
#define Gn   1024
#define DATT 612
#define N1   (Bn*Sn)
#define M1   (N1*Ln)
#define DIN1 (En+Pn)
#define NBATT 5             // 640/128
#define XKP  416            // padded K for x (400)
#define ZKP  640            // padded K/N for 612

typedef unsigned long long u64;

// ---------------- scratch (device globals) ----------------------------------
__device__ float d_gpre[2*M1*Gn];
__device__ float d_z[M1*DATT];
__device__ float d_scp[M1*NBATT];
__device__ float d_scores[M1];
__device__ float d_senvec[N1*2*Hn];
__device__ float d_gpre2[2*N1*Gn];
__device__ float d_z2[N1*DATT];
__device__ float d_hT[2*Bn*Hn];
__device__ float d_scp2[N1*NBATT];
__device__ float d_scores2[N1];
__device__ float d_docvec[Bn*2*Hn];
__device__ float d_brep[16*Gn];     // replicated bias (16 identical rows)
__device__ __half g_wtf[Hn*Gn];     // Whh fp16, layout [k][unit][gate]
__device__ __half g_wtb[Hn*Gn];
__device__ __half g_stf[Hn*Gn];
__device__ __half g_stb[Hn*Gn];
__device__ __half g_x[M1*XKP];
__device__ __half g_zb[(size_t)M1*ZKP];
__device__ __half g_sx[N1*ZKP];
__device__ __half g_z2b[N1*ZKP];
__device__ __half g_wihf[Gn*XKP];
__device__ __half g_wihb[Gn*XKP];
__device__ __half g_sihf[Gn*ZKP];
__device__ __half g_sihb[Gn*ZKP];
__device__ __half g_wWt[ZKP*ZKP];
__device__ __half g_sWt[ZKP*ZKP];

__device__ __forceinline__ float sigmoidf(float x) { return 1.0f / (1.0f + expf(-x)); }

__device__ __forceinline__ void fma2(u64& d, u64 a, u64 b) {
    asm("fma.rn.f32x2 %0, %1, %2, %3;" : "=l"(d) : "l"(a), "l"(b), "l"(d));
}
__device__ __forceinline__ u64 pack2(float x, float y) {
    u64 r; asm("mov.b64 %0, {%1,%2};" : "=l"(r) : "f"(x), "f"(y)); return r;
}
__device__ __forceinline__ void unpack2(float& lo, float& hi, u64 v) {
    asm("mov.b64 {%0,%1}, %2;" : "=f"(lo), "=f"(hi) : "l"(v));
}
__device__ __forceinline__ uint32_t smem_u32(const void* p) {
    return (uint32_t)__cvta_generic_to_shared(p);
}
__device__ __forceinline__ void cp16(uint32_t dst, const void* src) {
    asm volatile("cp.async.cg.shared.global [%0], [%1], 16;" :: "r"(dst), "l"(src));
}
#define CP_COMMIT() asm volatile("cp.async.commit_group;" ::: "memory")
#define CP_WAIT0()  asm volatile("cp.async.wait_group 0;" ::: "memory")

// ======================= WMMA fp16 GEMM, 128x128 tile ========================
// (identical to R15: 2-stage cp.async, K-step 32, pad-40 rows, 2 CTAs/SM)
#define TSEH  5120
#define SSEH  10240
#define GEMM_SMEM2 66560

__global__ __launch_bounds__(256, 2)
void gemm_h(const __half* __restrict__ A, const __half* __restrict__ B,
            const float* __restrict__ brep, const float* __restrict__ bias,
            const float* __restrict__ proj,
            float* __restrict__ C, int M, int Nc, int KP, int Nv, int attn)
{
    extern __shared__ float dynsm[];
    __half* sb  = (__half*)dynsm;
    float* outs = dynsm;
    float* red  = dynsm + 16384;

    const int tid = threadIdx.x;
    const int m0 = blockIdx.y * 128;
    const int n0 = blockIdx.x * 128;
    const int w  = tid >> 5;
    const int wm = w >> 1;
    const int wn = w & 1;

    wmma::fragment<wmma::accumulator, 16, 16, 16, float> acc[2][4];
    if (attn == 0) {
#pragma unroll
        for (int i = 0; i < 2; i++)
#pragma unroll
            for (int j = 0; j < 4; j++)
                wmma::load_matrix_sync(acc[i][j], brep + n0 + wn*64 + j*16, Gn,
                                       wmma::mem_row_major);
    } else {
#pragma unroll
        for (int i = 0; i < 2; i++)
#pragma unroll
            for (int j = 0; j < 4; j++)
                wmma::fill_fragment(acc[i][j], 0.0f);
    }

    const int nk   = KP / 32;
    const int rowi = tid >> 1;
    const int kof  = (tid & 1) * 16;
    const uint32_t sbase = smem_u32(sb);
    const uint32_t boff  = (uint32_t)(rowi * 80 + kof * 2);

    const __half* __restrict__ pa = A + (size_t)(m0 + rowi) * KP + kof;
    const __half* __restrict__ pb = B + (size_t)(n0 + rowi) * KP + kof;

    {
        const uint32_t d0 = sbase + boff;
        cp16(d0 +     0, pa);     cp16(d0 +    16, pa + 8);
        cp16(d0 + 10240, pb);     cp16(d0 + 10240 + 16, pb + 8);
        CP_COMMIT();
        CP_WAIT0();
    }
    __syncthreads();

    for (int kc = 0; kc < nk; kc++) {
        const int cur = kc & 1;
        if (kc + 1 < nk) {
            const int go = (kc + 1) * 32;
            const uint32_t d1 = sbase + (uint32_t)((cur ^ 1) * 20480) + boff;
            cp16(d1 +     0, pa + go);     cp16(d1 +    16, pa + go + 8);
            cp16(d1 + 10240, pb + go);     cp16(d1 + 10240 + 16, pb + go + 8);
            CP_COMMIT();
        }
        const __half* Ah = sb + cur * SSEH;
        const __half* Bh = Ah + TSEH;
#pragma unroll
        for (int kf = 0; kf < 2; kf++) {
            wmma::fragment<wmma::matrix_a, 16, 16, 16, __half, wmma::row_major> ah[2];
#pragma unroll
            for (int i = 0; i < 2; i++) {
                wmma::load_matrix_sync(ah[i], Ah + (wm*32 + i*16)*40 + kf*16, 40);
            }
#pragma unroll
            for (int j = 0; j < 4; j++) {
                wmma::fragment<wmma::matrix_b, 16, 16, 16, __half, wmma::col_major> bh;
                wmma::load_matrix_sync(bh, Bh + (wn*64 + j*16)*40 + kf*16, 40);
#pragma unroll
                for (int i = 0; i < 2; i++) {
                    wmma::mma_sync(acc[i][j], ah[i], bh, acc[i][j]);
                }
            }
        }
        if (kc + 1 < nk) CP_WAIT0();
        __syncthreads();
    }

    if (attn == 0) {
#pragma unroll
        for (int i = 0; i < 2; i++)
#pragma unroll
            for (int j = 0; j < 4; j++)
                wmma::store_matrix_sync(
                    C + (size_t)(m0 + wm*32 + i*16) * Nc + n0 + wn*64 + j*16,
                    acc[i][j], Nc, wmma::mem_row_major);
    } else {
#pragma unroll
        for (int i = 0; i < 2; i++)
#pragma unroll
            for (int j = 0; j < 4; j++)
                wmma::store_matrix_sync(outs + (size_t)(wm*32 + i*16)*128 + wn*64 + j*16,
                                        acc[i][j], 128, wmma::mem_row_major);
        __syncthreads();
        const int row = tid >> 1;
        const int hf  = (tid & 1) * 64;
        float part = 0.f;
#pragma unroll
        for (int c = 0; c < 64; c++) {
            int n = n0 + hf + c;
            if (n < Nv) part += tanhf(outs[row*128 + hf + c] + bias[n]) * proj[n];
        }
        red[tid] = part;
        __syncthreads();
        if (tid < 128) {
            C[(size_t)(m0 + tid) * gridDim.x + blockIdx.x] = red[2*tid] + red[2*tid + 1];
        }
    }
}

// ---------------- bias replication (16 identical rows) ------------------------
__global__ void rep_bias(const float* __restrict__ bias, int Nc)
{
    int idx = blockIdx.x * blockDim.x + threadIdx.x;
    if (idx >= 16 * Nc) return;
    d_brep[(idx / Nc) * Gn + (idx % Nc)] = bias[idx % Nc];
}

// ---------------- gather: x fp16 + z pos cols fp16 ----------------------------
__global__ void gather_x_kernel(const int* __restrict__ tok,
                                const int* __restrict__ wpos,
                                const float* __restrict__ emb,
                                const float* __restrict__ wpe)
{
    int idx = blockIdx.x * blockDim.x + threadIdx.x;
    if (idx >= M1 * DIN1) return;
    int d = idx % DIN1;
    int m = idx / DIN1;
    float v;
    if (d < En) {
        v = emb[(size_t)tok[m] * En + d];
    } else {
        v = wpe[(size_t)wpos[m] * Pn + (d - En)];
        g_zb[(size_t)m * ZKP + 2*Hn + (d - En)] = __float2half(v);
    }
    g_x[(size_t)m * XKP + d] = __float2half(v);
}

__global__ void pad_x_kernel()
{
    int idx = blockIdx.x * blockDim.x + threadIdx.x;
    if (idx >= M1 * (XKP - DIN1)) return;
    int m = idx / (XKP - DIN1);
    int k = DIN1 + idx % (XKP - DIN1);
    g_x[(size_t)m * XKP + k] = __float2half(0.f);
}

__global__ void pad_z_kernel()
{
    int idx = blockIdx.x * blockDim.x + threadIdx.x;
    if (idx >= M1 * (ZKP - DATT)) return;
    int m = idx / (ZKP - DATT);
    int k = DATT + idx % (ZKP - DATT);
    g_zb[(size_t)m * ZKP + k] = __float2half(0.f);
}

// ---------------- weight conversions -------------------------------------------
__global__ void conv_pad(const float* __restrict__ W, __half* __restrict__ out,
                         int rows, int kc, int kp)
{
    int idx = blockIdx.x * blockDim.x + threadIdx.x;
    if (idx >= rows * kp) return;
    int r = idx / kp;
    int k = idx % kp;
    float v = (k < kc) ? W[(size_t)r * kc + k] : 0.f;
    out[idx] = __float2half(v);
}

__global__ void conv_wt(const float* __restrict__ W, __half* __restrict__ out,
                        int d, int np, int kp)
{
    int idx = blockIdx.x * blockDim.x + threadIdx.x;
    if (idx >= np * kp) return;
    int e = idx / kp;
    int k = idx % kp;
    float v = (e < d && k < d) ? W[(size_t)k * d + e] : 0.f;
    out[idx] = __float2half(v);
}

// Whh [1024 rows=(gate*256+unit)][256 cols=k] -> fp16 [k][unit*4 + gate]
__global__ void conv_whh(const float* __restrict__ W, __half* __restrict__ out)
{
    int idx = blockIdx.x * blockDim.x + threadIdx.x;
    if (idx >= Hn * Gn) return;
    int k = idx / Gn;
    int r = idx % Gn;
    int c = r >> 2;        // unit
    int g = r & 3;         // gate
    out[idx] = __float2half(W[(size_t)(g * 256 + c) * Hn + k]);
}

// ---------------- word BiLSTM scan (8 rows/block, fp16 Whh) --------------------
__global__ __launch_bounds__(256, 1)
void lstm_scan_w(const float* __restrict__ gpre,
                 const __half* __restrict__ Wt_f,
                 const __half* __restrict__ Wt_b,
                 float* __restrict__ out,
                 __half* __restrict__ zh,
                 int N, int T, int ostride)
{
    extern __shared__ float dynsm[];
    __half* wsh = (__half*)dynsm;        // [2][8][1024] halves = 32768 B
    float* hs = dynsm + 8192;            // [256][8]
    const int tid = threadIdx.x;
    const int nb  = N / 8;
    const int dir = blockIdx.x / nb;
    const int n0  = (blockIdx.x % nb) * 8;
    const __half* __restrict__ Wt = dir ? Wt_b : Wt_f;

    float c[8];
#pragma unroll
    for (int r = 0; r < 8; r++) c[r] = 0.f;
    for (int i = tid; i < 256*8; i += 256) hs[i] = 0.f;

#pragma unroll
    for (int i = 0; i < 4; i++) {
        *(uint4*)&wsh[(tid + 256*i)*8] = *(const uint4*)&Wt[(tid + 256*i)*8];
    }
    __syncthreads();

    const int NT = 32;
    for (int step = 0; step < T; step++) {
        const int tt = dir ? (T - 1 - step) : step;
        u64 acc2[4][4];
#pragma unroll
        for (int rp = 0; rp < 4; rp++) {
            size_t b0 = ((size_t)(dir*N + n0 + rp*2    ) * T + tt) * Gn;
            size_t b1 = ((size_t)(dir*N + n0 + rp*2 + 1) * T + tt) * Gn;
#pragma unroll
            for (int g = 0; g < 4; g++) {
                acc2[rp][g] = pack2(gpre[b0 + g*256 + tid], gpre[b1 + g*256 + tid]);
            }
        }
        for (int kt = 0; kt < NT; kt++) {
            const int cur = kt & 1;
            const bool last = (step == T-1) && (kt == NT-1);
            uint4 pf[4];
            if (!last) {
                const __half* src = &Wt[(size_t)((kt + 1) & 31) * 8192];
#pragma unroll
                for (int i = 0; i < 4; i++) {
                    pf[i] = *(const uint4*)&src[(tid + 256*i)*8];
                }
            }
#pragma unroll
            for (int kk = 0; kk < 8; kk++) {
                const int k = kt*8 + kk;
                const __half* wrow = &wsh[(cur*8 + kk)*1024];
                u64 wv = *(const u64*)(wrow + tid*4);
                uint32_t lo32 = (uint32_t)wv;
                uint32_t hi32 = (uint32_t)(wv >> 32);
                float2 f01 = __half22float2(*(__half2*)&lo32);
                float2 f23 = __half22float2(*(__half2*)&hi32);
                u64 wd0 = pack2(f01.x, f01.x);
                u64 wd1 = pack2(f01.y, f01.y);
                u64 wd2 = pack2(f23.x, f23.x);
                u64 wd3 = pack2(f23.y, f23.y);
#pragma unroll
                for (int rp = 0; rp < 4; rp++) {
                    u64 h2 = *(const u64*)&hs[k*8 + rp*2];
                    fma2(acc2[rp][0], h2, wd0);
                    fma2(acc2[rp][1], h2, wd1);
                    fma2(acc2[rp][2], h2, wd2);
                    fma2(acc2[rp][3], h2, wd3);
                }
            }
            if (!last) {
                __half* dst = &wsh[(cur ^ 1) * 8192];
#pragma unroll
                for (int i = 0; i < 4; i++) {
                    *(uint4*)&dst[(tid + 256*i)*8] = pf[i];
                }
            }
            __syncthreads();
        }
#pragma unroll
        for (int rp = 0; rp < 4; rp++) {
            float p0[2];
            float p1[2];
            float p2[2];
            float p3[2];
            unpack2(p0[0], p0[1], acc2[rp][0]);
            unpack2(p1[0], p1[1], acc2[rp][1]);
            unpack2(p2[0], p2[1], acc2[rp][2]);
            unpack2(p3[0], p3[1], acc2[rp][3]);
#pragma unroll
            for (int hh = 0; hh < 2; hh++) {
                int r = rp*2 + hh;
                float iv = sigmoidf(p0[hh]);
                float fv = sigmoidf(p1[hh]);
                float gv = tanhf(p2[hh]);
                float ov = sigmoidf(p3[hh]);
                c[r] = fv * c[r] + iv * gv;
                float hv = ov * tanhf(c[r]);
                hs[tid*8 + r] = hv;
                size_t mrow = (size_t)(n0 + r) * T + tt;
                out[mrow * ostride + dir*256 + tid] = hv;
                zh[mrow * ZKP + dir*256 + tid] = __float2half(hv);
            }
        }
        __syncthreads();
    }
}

// ---------------- sentence BiLSTM scan (1 row/block, fp16 Whh) ------------------
__global__ __launch_bounds__(256, 1)
void lstm_scan_s(const float* __restrict__ gpre,
                 const __half* __restrict__ Wt_f,
                 const __half* __restrict__ Wt_b,
                 float* __restrict__ out,
                 __half* __restrict__ zh,
                 float* __restrict__ hT,
                 int N, int T, int ostride)
{
    extern __shared__ float dynsm[];
    __half* wsh = (__half*)dynsm;
    float* hs = dynsm + 8192;
    const int tid = threadIdx.x;
    const int dir = blockIdx.x / N;
    const int n0  = blockIdx.x % N;
    const __half* __restrict__ Wt = dir ? Wt_b : Wt_f;

    float c0 = 0.f;
    hs[tid] = 0.f;

#pragma unroll
    for (int i = 0; i < 4; i++) {
        *(uint4*)&wsh[(tid + 256*i)*8] = *(const uint4*)&Wt[(tid + 256*i)*8];
    }
    __syncthreads();

    const int NT = 32;
    for (int step = 0; step < T; step++) {
        const int tt = dir ? (T - 1 - step) : step;
        float acc[4];
        size_t b0 = ((size_t)(dir*N + n0) * T + tt) * Gn;
#pragma unroll
        for (int g = 0; g < 4; g++) {
            acc[g] = gpre[b0 + g*256 + tid];
        }
        for (int kt = 0; kt < NT; kt++) {
            const int cur = kt & 1;
            const bool last = (step == T-1) && (kt == NT-1);
            uint4 pf[4];
            if (!last) {
                const __half* src = &Wt[(size_t)((kt + 1) & 31) * 8192];
#pragma unroll
                for (int i = 0; i < 4; i++) {
                    pf[i] = *(const uint4*)&src[(tid + 256*i)*8];
                }
            }
#pragma unroll
            for (int kk = 0; kk < 8; kk++) {
                const int k = kt*8 + kk;
                const __half* wrow = &wsh[(cur*8 + kk)*1024];
                u64 wv = *(const u64*)(wrow + tid*4);
                uint32_t lo32 = (uint32_t)wv;
                uint32_t hi32 = (uint32_t)(wv >> 32);
                float2 f01 = __half22float2(*(__half2*)&lo32);
                float2 f23 = __half22float2(*(__half2*)&hi32);
                float hv = hs[k];
                acc[0] += hv * f01.x;
                acc[1] += hv * f01.y;
                acc[2] += hv * f23.x;
                acc[3] += hv * f23.y;
            }
            if (!last) {
                __half* dst = &wsh[(cur ^ 1) * 8192];
#pragma unroll
                for (int i = 0; i < 4; i++) {
                    *(uint4*)&dst[(tid + 256*i)*8] = pf[i];
                }
            }
            __syncthreads();
        }
        float iv = sigmoidf(acc[0]);
        float fv = sigmoidf(acc[1]);
        float gv = tanhf(acc[2]);
        float ov = sigmoidf(acc[3]);
        c0 = fv * c0 + iv * gv;
        float hv = ov * tanhf(c0);
        hs[tid] = hv;
        size_t mrow = (size_t)n0 * T + tt;
        out[mrow * ostride + dir*256 + tid] = hv;
        zh[mrow * ZKP + dir*256 + tid] = __float2half(hv);
        if (step == T - 1) {
            hT[((size_t)dir * N + n0) * 256 + tid] = hv;
        }
        __syncthreads();
    }
}

// ---------------- attention glue -----------------------------------------------
__global__ void sum_scores(const float* __restrict__ scp, float* __restrict__ sc,
                           int M, int NB)
{
    int m = blockIdx.x * blockDim.x + threadIdx.x;
    if (m >= M) return;
    float s = 0.f;
    for (int j = 0; j < NB; j++) s += scp[(size_t)m * NB + j];
    sc[m] = s;
}

__global__ void softmax_pool_kernel(const float* __restrict__ sc,
                                    const float* __restrict__ hsrc,
                                    float* __restrict__ outv,
                                    int T, int stride)
{
    __shared__ float a[64];
    __shared__ float inv_s;
    int n = blockIdx.x;
    int tid = threadIdx.x;
    if (tid == 0) {
        float mx = -1e30f;
        for (int t = 0; t < T; t++) mx = fmaxf(mx, sc[n * T + t]);
        float sum = 0.f;
        for (int t = 0; t < T; t++) {
            float e = expf(sc[n * T + t] - mx);
            a[t] = e;
            sum += e;
        }
        inv_s = 1.f / sum;
    }
    __syncthreads();
    float inv = inv_s;
    for (int col = tid; col < 2*Hn; col += blockDim.x) {
        float acc = 0.f;
        for (int t = 0; t < T; t++) {
            acc += a[t] * hsrc[((size_t)n * T + t) * stride + col];
        }
        outv[(size_t)n * (2*Hn) + col] = acc * inv;
    }
}

__global__ void build_sx_kernel(const int* __restrict__ seg,
                                const float* __restrict__ spe)
{
    int idx = blockIdx.x * blockDim.x + threadIdx.x;
    if (idx >= N1 * ZKP) return;
    int d = idx % ZKP;
    int m = idx / ZKP;
    float v;
    if (d < 2*Hn)      v = d_senvec[(size_t)m * (2*Hn) + d];
    else if (d < DATT) v = spe[(size_t)seg[m] * Pn + (d - 2*Hn)];
    else               v = 0.f;
    g_sx[idx] = __float2half(v);
}

__global__ void fill_z2pos(const int* __restrict__ seg, const float* __restrict__ spe)
{
    int idx = blockIdx.x * blockDim.x + threadIdx.x;
    if (idx >= N1 * (ZKP - 2*Hn)) return;
    int m = idx / (ZKP - 2*Hn);
    int d = idx % (ZKP - 2*Hn);
    float v = (d < Pn) ? spe[(size_t)seg[m] * Pn + d] : 0.f;
    g_z2b[(size_t)m * ZKP + 2*Hn + d] = __float2half(v);
}

// ---------------- classifier head ------------------------------------------------
__global__ void final_dense_kernel(const float* __restrict__ dW,
                                   const float* __restrict__ db,
                                   float* __restrict__ outp)
{
    __shared__ float r0[128];
    __shared__ float r1[128];
    __shared__ float r2[128];
    int b = blockIdx.x;
    int tid = threadIdx.x;
    float a0 = 0.f, a1 = 0.f, a2 = 0.f;
    for (int k = tid; k < 4*Hn; k += 128) {
        float f;
        if (k < 2*Hn)      f = d_docvec[b * 2*Hn + k];
        else if (k < 3*Hn) f = d_hT[(0 * Bn + b) * Hn + (k - 2*Hn)];
        else               f = d_hT[(1 * Bn + b) * Hn + (k - 3*Hn)];
        a0 += f * dW[0*4*Hn + k];
        a1 += f * dW[1*4*Hn + k];
        a2 += f * dW[2*4*Hn + k];
    }
    r0[tid] = a0;
    r1[tid] = a1;
    r2[tid] = a2;
    __syncthreads();
    for (int s = 64; s > 0; s >>= 1) {
        if (tid < s) {
            r0[tid] += r0[tid+s];
            r1[tid] += r1[tid+s];
            r2[tid] += r2[tid+s];
        }
        __syncthreads();
    }
    if (tid == 0) {
        outp[b*3+0] = r0[0] + db[0];
        outp[b*3+1] = r1[0] + db[1];
        outp[b*3+2] = r2[0] + db[2];
    }
}

// ---------------- host driver ------------------------------------------------------
extern "C" void kernel_launch(void* const* d_in, const int* in_sizes, int n_in,
                              void* d_out, int out_size)
{
    const int*   tok     = (const int*)d_in[0];
    const int*   wpos    = (const int*)d_in[1];
    const int*   seg     = (const int*)d_in[2];
    const float* emb     = (const float*)d_in[3];
    const float* wpe     = (const float*)d_in[4];
    const float* spe     = (const float*)d_in[5];
    const float* wWih_f  = (const float*)d_in[6];
    const float* wWhh_f  = (const float*)d_in[7];
    const float* wb_f    = (const float*)d_in[8];
    const float* wWih_b  = (const float*)d_in[9];
    const float* wWhh_b  = (const float*)d_in[10];
    const float* wb_b    = (const float*)d_in[11];
    const float* sWih_f  = (const float*)d_in[12];
    const float* sWhh_f  = (const float*)d_in[13];
    const float* sb_f    = (const float*)d_in[14];
    const float* sWih_b  = (const float*)d_in[15];
    const float* sWhh_b  = (const float*)d_in[16];
    const float* sb_b    = (const float*)d_in[17];
    const float* word_W  = (const float*)d_in[18];
    const float* word_b  = (const float*)d_in[19];
    const float* word_p  = (const float*)d_in[20];
    const float* sent_W  = (const float*)d_in[21];
    const float* sent_b  = (const float*)d_in[22];
    const float* sent_p  = (const float*)d_in[23];
    const float* dense_W = (const float*)d_in[24];
    const float* dense_b = (const float*)d_in[25];
    float* outp = (float*)d_out;

    float *pgpre, *pz, *pscp, *psc, *psenvec, *pgpre2, *pz2,
          *phT, *pscp2, *psc2, *pdocvec, *pbrep;
    __half *pwtf, *pwtb, *pstf, *pstb;
    __half *px, *pzb, *psx, *pz2b, *pwihf, *pwihb, *psihf, *psihb, *pwWt, *psWt;
    cudaGetSymbolAddress((void**)&pgpre,   d_gpre);
    cudaGetSymbolAddress((void**)&pz,      d_z);
    cudaGetSymbolAddress((void**)&pscp,    d_scp);
    cudaGetSymbolAddress((void**)&psc,     d_scores);
    cudaGetSymbolAddress((void**)&psenvec, d_senvec);
    cudaGetSymbolAddress((void**)&pgpre2,  d_gpre2);
    cudaGetSymbolAddress((void**)&pz2,     d_z2);
    cudaGetSymbolAddress((void**)&phT,     d_hT);
    cudaGetSymbolAddress((void**)&pscp2,   d_scp2);
    cudaGetSymbolAddress((void**)&psc2,    d_scores2);
    cudaGetSymbolAddress((void**)&pdocvec, d_docvec);
    cudaGetSymbolAddress((void**)&pbrep,   d_brep);
    cudaGetSymbolAddress((void**)&pwtf,    g_wtf);
    cudaGetSymbolAddress((void**)&pwtb,    g_wtb);
    cudaGetSymbolAddress((void**)&pstf,    g_stf);
    cudaGetSymbolAddress((void**)&pstb,    g_stb);
    cudaGetSymbolAddress((void**)&px,      g_x);
    cudaGetSymbolAddress((void**)&pzb,     g_zb);
    cudaGetSymbolAddress((void**)&psx,     g_sx);
    cudaGetSymbolAddress((void**)&pz2b,    g_z2b);
    cudaGetSymbolAddress((void**)&pwihf,   g_wihf);
    cudaGetSymbolAddress((void**)&pwihb,   g_wihb);
    cudaGetSymbolAddress((void**)&psihf,   g_sihf);
    cudaGetSymbolAddress((void**)&psihb,   g_sihb);
    cudaGetSymbolAddress((void**)&pwWt,    g_wWt);
    cudaGetSymbolAddress((void**)&psWt,    g_sWt);

    cudaFuncSetAttribute(lstm_scan_w, cudaFuncAttributeMaxDynamicSharedMemorySize,
                         32768 + 256*8*4);
    cudaFuncSetAttribute(lstm_scan_s, cudaFuncAttributeMaxDynamicSharedMemorySize,
                         32768 + 256*4);
    cudaFuncSetAttribute(gemm_h, cudaFuncAttributeMaxDynamicSharedMemorySize,
                         GEMM_SMEM2);

    // 1. gather + padding
    gather_x_kernel<<<(M1*DIN1 + 255)/256, 256>>>(tok, wpos, emb, wpe);
    pad_x_kernel<<<(M1*(XKP-DIN1) + 255)/256, 256>>>();
    pad_z_kernel<<<(M1*(ZKP-DATT) + 255)/256, 256>>>();

    // 2. weight conversions
    conv_pad<<<(Gn*XKP + 255)/256, 256>>>(wWih_f, pwihf, Gn, DIN1, XKP);
    conv_pad<<<(Gn*XKP + 255)/256, 256>>>(wWih_b, pwihb, Gn, DIN1, XKP);
    conv_pad<<<(Gn*ZKP + 255)/256, 256>>>(sWih_f, psihf, Gn, DATT, ZKP);
    conv_pad<<<(Gn*ZKP + 255)/256, 256>>>(sWih_b, psihb, Gn, DATT, ZKP);
    conv_wt<<<(ZKP*ZKP + 255)/256, 256>>>(word_W, pwWt, DATT, ZKP, ZKP);
    conv_wt<<<(ZKP*ZKP + 255)/256, 256>>>(sent_W, psWt, DATT, ZKP, ZKP);
    conv_whh<<<(Hn*Gn + 255)/256, 256>>>(wWhh_f, pwtf);
    conv_whh<<<(Hn*Gn + 255)/256, 256>>>(wWhh_b, pwtb);
    conv_whh<<<(Hn*Gn + 255)/256, 256>>>(sWhh_f, pstf);
    conv_whh<<<(Hn*Gn + 255)/256, 256>>>(sWhh_b, pstb);

    // 3. word input GEMMs
    {
        dim3 g(Gn/128, M1/128);
        rep_bias<<<(16*Gn + 255)/256, 256>>>(wb_f, Gn);
        gemm_h<<<g, 256, GEMM_SMEM2>>>(px, pwihf, pbrep, (const float*)0,
                                       (const float*)0, pgpre, M1, Gn, XKP, Gn, 0);
        rep_bias<<<(16*Gn + 255)/256, 256>>>(wb_b, Gn);
        gemm_h<<<g, 256, GEMM_SMEM2>>>(px, pwihb, pbrep, (const float*)0,
                                       (const float*)0,
                                       pgpre + (size_t)M1*Gn, M1, Gn, XKP, Gn, 0);
    }

    // 4. word BiLSTM scan -> d_z fp32 + z fp16
    lstm_scan_w<<<128, 256, 32768 + 256*8*4>>>(pgpre, pwtf, pwtb, pz,
                                               pzb, N1, Ln, DATT);

    // 5. word attention
    gemm_h<<<dim3(NBATT, M1/128), 256, GEMM_SMEM2>>>(pzb, pwWt, (const float*)0,
                                                     word_b, word_p,
                                                     pscp, M1, ZKP, ZKP, DATT, 1);
    sum_scores<<<(M1 + 255)/256, 256>>>(pscp, psc, M1, NBATT);
    softmax_pool_kernel<<<N1, 256>>>(psc, pz, psenvec, Ln, DATT);

    // 6. sentence input
    build_sx_kernel<<<(N1*ZKP + 255)/256, 256>>>(seg, spe);
    fill_z2pos<<<(N1*(ZKP-2*Hn) + 255)/256, 256>>>(seg, spe);
    {
        dim3 g(Gn/128, N1/128);
        rep_bias<<<(16*Gn + 255)/256, 256>>>(sb_f, Gn);
        gemm_h<<<g, 256, GEMM_SMEM2>>>(psx, psihf, pbrep, (const float*)0,
                                       (const float*)0, pgpre2, N1, Gn, ZKP, Gn, 0);
        rep_bias<<<(16*Gn + 255)/256, 256>>>(sb_b, Gn);
        gemm_h<<<g, 256, GEMM_SMEM2>>>(psx, psihb, pbrep, (const float*)0,
                                       (const float*)0,
                                       pgpre2 + (size_t)N1*Gn, N1, Gn, ZKP, Gn, 0);
    }

    // 7. sentence BiLSTM scan -> d_z2 fp32 + z2 fp16, keeps hT
    lstm_scan_s<<<2*Bn, 256, 32768 + 256*4>>>(pgpre2, pstf, pstb, pz2,
                                              pz2b, phT, Bn, Sn, DATT);

    // 8. sentence attention
    gemm_h<<<dim3(NBATT, N1/128), 256, GEMM_SMEM2>>>(pz2b, psWt, (const float*)0,
                                                     sent_b, sent_p,
                                                     pscp2, N1, ZKP, ZKP, DATT, 1);
    sum_scores<<<(N1 + 255)/256, 256>>>(pscp2, psc2, N1, NBATT);
    softmax_pool_kernel<<<Bn, 256>>>(psc2, pz2, pdocvec, Sn, DATT);

    // 9. classifier head
    final_dense_kernel<<<Bn, 128>>>(dense_W, dense_b, outp);
}

// round 17
// speedup vs baseline: 1.7791x; 1.0318x over previous
#include <cuda_runtime.h>
#include <cuda_fp16.h>
#include <mma.h>
#include <cstdint>
#include <math.h>

using namespace nvcuda;

// ---------------- problem constants ----------------
#define Bn   32
#define Sn   16
#define Ln   64
#define En   300
#define Pn   100
#define Hn   256
#define Gn   1024
#define G2   2048           // fused fwd|bwd gate width
#define DATT 612
#define N1   (Bn*Sn)
#define M1   (N1*Ln)
#define DIN1 (En+Pn)
#define NBATT 5             // 640/128
#define XKP  416            // padded K for x (400)
#define ZKP  640            // padded K/N for 612

typedef unsigned long long u64;

// ---------------- scratch (device globals) ----------------------------------
__device__ float d_gpre[(size_t)M1*G2];   // [m][dir*1024 + gate*256 + unit]
__device__ float d_z[M1*DATT];
__device__ float d_scp[M1*NBATT];
__device__ float d_scores[M1];
__device__ float d_senvec[N1*2*Hn];
__device__ float d_gpre2[N1*G2];
__device__ float d_z2[N1*DATT];
__device__ float d_hT[2*Bn*Hn];
__device__ float d_scp2[N1*NBATT];
__device__ float d_scores2[N1];
__device__ float d_docvec[Bn*2*Hn];
__device__ float d_brep[16*G2];           // replicated concat bias (16 rows)
__device__ __half g_wtf[Hn*Gn];           // Whh fp16, layout [k][unit][gate]
__device__ __half g_wtb[Hn*Gn];
__device__ __half g_stf[Hn*Gn];
__device__ __half g_stb[Hn*Gn];
__device__ __half g_x[M1*XKP];
__device__ __half g_zb[(size_t)M1*ZKP];
__device__ __half g_sx[N1*ZKP];
__device__ __half g_z2b[N1*ZKP];
__device__ __half g_wih[G2*XKP];          // concat fwd|bwd word Wih
__device__ __half g_sih[G2*ZKP];          // concat fwd|bwd sentence Wih
__device__ __half g_wWt[ZKP*ZKP];
__device__ __half g_sWt[ZKP*ZKP];

__device__ __forceinline__ float sigmoidf(float x) { return 1.0f / (1.0f + expf(-x)); }

__device__ __forceinline__ void fma2(u64& d, u64 a, u64 b) {
    asm("fma.rn.f32x2 %0, %1, %2, %3;" : "=l"(d) : "l"(a), "l"(b), "l"(d));
}
__device__ __forceinline__ u64 pack2(float x, float y) {
    u64 r; asm("mov.b64 %0, {%1,%2};" : "=l"(r) : "f"(x), "f"(y)); return r;
}
__device__ __forceinline__ void unpack2(float& lo, float& hi, u64 v) {
    asm("mov.b64 {%0,%1}, %2;" : "=f"(lo), "=f"(hi) : "l"(v));
}
__device__ __forceinline__ uint32_t smem_u32(const void* p) {
    return (uint32_t)__cvta_generic_to_shared(p);
}
__device__ __forceinline__ void cp16(uint32_t dst, const void* src) {
    asm volatile("cp.async.cg.shared.global [%0], [%1], 16;" :: "r"(dst), "l"(src));
}
#define CP_COMMIT() asm volatile("cp.async.commit_group;" ::: "memory")
#define CP_WAIT0()  asm volatile("cp.async.wait_group 0;" ::: "memory")
#define CP_WAIT1()  asm volatile("cp.async.wait_group 1;" ::: "memory")

// ======================= WMMA fp16 GEMM, 128x128 tile, 3-stage ===============
// C[M,Nc] = A[M,KP] @ B[*,KP]^T, fp16 in / fp32 acc, KP mult 32, M/Nc mult 128.
// 3-stage cp.async (stage stride 20480B), K-step 32, pad-40 rows, 2 CTAs/SM.
// attn==0: acc init from brep (ldm Nc) -> direct global store.
// attn!=0: smem out tile + tanh/proj row-reduction.
#define TSEH  5120
#define SSEH  10240           // stage stride in halves (20480 B)
#define GEMM_SMEM2 66560

__global__ __launch_bounds__(256, 2)
void gemm_h(const __half* __restrict__ A, const __half* __restrict__ B,
            const float* __restrict__ brep, const float* __restrict__ bias,
            const float* __restrict__ proj,
            float* __restrict__ C, int M, int Nc, int KP, int Nv, int attn)
{
    extern __shared__ float dynsm[];
    __half* sb  = (__half*)dynsm;
    float* outs = dynsm;
    float* red  = dynsm + 16384;

    const int tid = threadIdx.x;
    const int m0 = blockIdx.y * 128;
    const int n0 = blockIdx.x * 128;
    const int w  = tid >> 5;
    const int wm = w >> 1;
    const int wn = w & 1;

    wmma::fragment<wmma::accumulator, 16, 16, 16, float> acc[2][4];
    if (attn == 0) {
#pragma unroll
        for (int i = 0; i < 2; i++)
#pragma unroll
            for (int j = 0; j < 4; j++)
                wmma::load_matrix_sync(acc[i][j], brep + n0 + wn*64 + j*16, Nc,
                                       wmma::mem_row_major);
    } else {
#pragma unroll
        for (int i = 0; i < 2; i++)
#pragma unroll
            for (int j = 0; j < 4; j++)
                wmma::fill_fragment(acc[i][j], 0.0f);
    }

    const int nk   = KP / 32;
    const int rowi = tid >> 1;
    const int kof  = (tid & 1) * 16;
    const uint32_t sbase = smem_u32(sb);
    const uint32_t boff  = (uint32_t)(rowi * 80 + kof * 2);

    const __half* __restrict__ pa = A + (size_t)(m0 + rowi) * KP + kof;
    const __half* __restrict__ pb = B + (size_t)(n0 + rowi) * KP + kof;

    // prologue: stage chunks 0 and 1
    {
        const uint32_t d0 = sbase + boff;
        cp16(d0 +     0, pa);     cp16(d0 +    16, pa + 8);
        cp16(d0 + 10240, pb);     cp16(d0 + 10240 + 16, pb + 8);
        CP_COMMIT();
        if (1 < nk) {
            const uint32_t d1 = sbase + 20480u + boff;
            cp16(d1 +     0, pa + 32);     cp16(d1 +    16, pa + 40);
            cp16(d1 + 10240, pb + 32);     cp16(d1 + 10240 + 16, pb + 40);
        }
        CP_COMMIT();
        CP_WAIT1();            // chunk 0 complete (chunk 1 may be in flight)
    }
    __syncthreads();

    for (int kc = 0; kc < nk; kc++) {
        const int cur = kc % 3;
        if (kc + 2 < nk) {
            const int go = (kc + 2) * 32;
            const uint32_t d2 = sbase + (uint32_t)(((kc + 2) % 3) * 20480) + boff;
            cp16(d2 +     0, pa + go);     cp16(d2 +    16, pa + go + 8);
            cp16(d2 + 10240, pb + go);     cp16(d2 + 10240 + 16, pb + go + 8);
            CP_COMMIT();
        }
        const __half* Ah = sb + cur * SSEH;
        const __half* Bh = Ah + TSEH;
#pragma unroll
        for (int kf = 0; kf < 2; kf++) {
            wmma::fragment<wmma::matrix_a, 16, 16, 16, __half, wmma::row_major> ah[2];
#pragma unroll
            for (int i = 0; i < 2; i++) {
                wmma::load_matrix_sync(ah[i], Ah + (wm*32 + i*16)*40 + kf*16, 40);
            }
#pragma unroll
            for (int j = 0; j < 4; j++) {
                wmma::fragment<wmma::matrix_b, 16, 16, 16, __half, wmma::col_major> bh;
                wmma::load_matrix_sync(bh, Bh + (wn*64 + j*16)*40 + kf*16, 40);
#pragma unroll
                for (int i = 0; i < 2; i++) {
                    wmma::mma_sync(acc[i][j], ah[i], bh, acc[i][j]);
                }
            }
        }
        if (kc + 1 < nk) {
            if (kc + 2 < nk) { CP_WAIT1(); }   // chunk kc+1 done, kc+2 in flight
            else            { CP_WAIT0(); }    // tail: only kc+1 outstanding
        }
        __syncthreads();
    }

    if (attn == 0) {
#pragma unroll
        for (int i = 0; i < 2; i++)
#pragma unroll
            for (int j = 0; j < 4; j++)
                wmma::store_matrix_sync(
                    C + (size_t)(m0 + wm*32 + i*16) * Nc + n0 + wn*64 + j*16,
                    acc[i][j], Nc, wmma::mem_row_major);
    } else {
#pragma unroll
        for (int i = 0; i < 2; i++)
#pragma unroll
            for (int j = 0; j < 4; j++)
                wmma::store_matrix_sync(outs + (size_t)(wm*32 + i*16)*128 + wn*64 + j*16,
                                        acc[i][j], 128, wmma::mem_row_major);
        __syncthreads();
        const int row = tid >> 1;
        const int hf  = (tid & 1) * 64;
        float part = 0.f;
#pragma unroll
        for (int c = 0; c < 64; c++) {
            int n = n0 + hf + c;
            if (n < Nv) part += tanhf(outs[row*128 + hf + c] + bias[n]) * proj[n];
        }
        red[tid] = part;
        __syncthreads();
        if (tid < 128) {
            C[(size_t)(m0 + tid) * gridDim.x + blockIdx.x] = red[2*tid] + red[2*tid + 1];
        }
    }
}

// ---------------- concat bias replication (16 rows of [bf|bb]) ----------------
__global__ void rep_bias2(const float* __restrict__ bf, const float* __restrict__ bb)
{
    int idx = blockIdx.x * blockDim.x + threadIdx.x;
    if (idx >= 16 * G2) return;
    int c = idx % G2;
    d_brep[idx] = (c < Gn) ? bf[c] : bb[c - Gn];
}

// ---------------- gather: x fp16 + z pos cols fp16 ----------------------------
__global__ void gather_x_kernel(const int* __restrict__ tok,
                                const int* __restrict__ wpos,
                                const float* __restrict__ emb,
                                const float* __restrict__ wpe)
{
    int idx = blockIdx.x * blockDim.x + threadIdx.x;
    if (idx >= M1 * DIN1) return;
    int d = idx % DIN1;
    int m = idx / DIN1;
    float v;
    if (d < En) {
        v = emb[(size_t)tok[m] * En + d];
    } else {
        v = wpe[(size_t)wpos[m] * Pn + (d - En)];
        g_zb[(size_t)m * ZKP + 2*Hn + (d - En)] = __float2half(v);
    }
    g_x[(size_t)m * XKP + d] = __float2half(v);
}

__global__ void pad_x_kernel()
{
    int idx = blockIdx.x * blockDim.x + threadIdx.x;
    if (idx >= M1 * (XKP - DIN1)) return;
    int m = idx / (XKP - DIN1);
    int k = DIN1 + idx % (XKP - DIN1);
    g_x[(size_t)m * XKP + k] = __float2half(0.f);
}

__global__ void pad_z_kernel()
{
    int idx = blockIdx.x * blockDim.x + threadIdx.x;
    if (idx >= M1 * (ZKP - DATT)) return;
    int m = idx / (ZKP - DATT);
    int k = DATT + idx % (ZKP - DATT);
    g_zb[(size_t)m * ZKP + k] = __float2half(0.f);
}

// ---------------- weight conversions -------------------------------------------
__global__ void conv_pad(const float* __restrict__ W, __half* __restrict__ out,
                         int rows, int kc, int kp)
{
    int idx = blockIdx.x * blockDim.x + threadIdx.x;
    if (idx >= rows * kp) return;
    int r = idx / kp;
    int k = idx % kp;
    float v = (k < kc) ? W[(size_t)r * kc + k] : 0.f;
    out[idx] = __float2half(v);
}

__global__ void conv_wt(const float* __restrict__ W, __half* __restrict__ out,
                        int d, int np, int kp)
{
    int idx = blockIdx.x * blockDim.x + threadIdx.x;
    if (idx >= np * kp) return;
    int e = idx / kp;
    int k = idx % kp;
    float v = (e < d && k < d) ? W[(size_t)k * d + e] : 0.f;
    out[idx] = __float2half(v);
}

// Whh [1024 rows=(gate*256+unit)][256 cols=k] -> fp16 [k][unit*4 + gate]
__global__ void conv_whh(const float* __restrict__ W, __half* __restrict__ out)
{
    int idx = blockIdx.x * blockDim.x + threadIdx.x;
    if (idx >= Hn * Gn) return;
    int k = idx / Gn;
    int r = idx % Gn;
    int c = r >> 2;
    int g = r & 3;
    out[idx] = __float2half(W[(size_t)(g * 256 + c) * Hn + k]);
}

// ---------------- word BiLSTM scan (8 rows/block, fp16 Whh, fused gpre) --------
__global__ __launch_bounds__(256, 1)
void lstm_scan_w(const float* __restrict__ gpre,
                 const __half* __restrict__ Wt_f,
                 const __half* __restrict__ Wt_b,
                 float* __restrict__ out,
                 __half* __restrict__ zh,
                 int N, int T, int ostride)
{
    extern __shared__ float dynsm[];
    __half* wsh = (__half*)dynsm;
    float* hs = dynsm + 8192;
    const int tid = threadIdx.x;
    const int nb  = N / 8;
    const int dir = blockIdx.x / nb;
    const int n0  = (blockIdx.x % nb) * 8;
    const __half* __restrict__ Wt = dir ? Wt_b : Wt_f;
    const int goff = dir * Gn;

    float c[8];
#pragma unroll
    for (int r = 0; r < 8; r++) c[r] = 0.f;
    for (int i = tid; i < 256*8; i += 256) hs[i] = 0.f;

#pragma unroll
    for (int i = 0; i < 4; i++) {
        *(uint4*)&wsh[(tid + 256*i)*8] = *(const uint4*)&Wt[(tid + 256*i)*8];
    }
    __syncthreads();

    const int NT = 32;
    for (int step = 0; step < T; step++) {
        const int tt = dir ? (T - 1 - step) : step;
        u64 acc2[4][4];
#pragma unroll
        for (int rp = 0; rp < 4; rp++) {
            size_t b0 = ((size_t)(n0 + rp*2    ) * T + tt) * G2 + goff;
            size_t b1 = ((size_t)(n0 + rp*2 + 1) * T + tt) * G2 + goff;
#pragma unroll
            for (int g = 0; g < 4; g++) {
                acc2[rp][g] = pack2(gpre[b0 + g*256 + tid], gpre[b1 + g*256 + tid]);
            }
        }
        for (int kt = 0; kt < NT; kt++) {
            const int cur = kt & 1;
            const bool last = (step == T-1) && (kt == NT-1);
            uint4 pf[4];
            if (!last) {
                const __half* src = &Wt[(size_t)((kt + 1) & 31) * 8192];
#pragma unroll
                for (int i = 0; i < 4; i++) {
                    pf[i] = *(const uint4*)&src[(tid + 256*i)*8];
                }
            }
#pragma unroll
            for (int kk = 0; kk < 8; kk++) {
                const int k = kt*8 + kk;
                const __half* wrow = &wsh[(cur*8 + kk)*1024];
                u64 wv = *(const u64*)(wrow + tid*4);
                uint32_t lo32 = (uint32_t)wv;
                uint32_t hi32 = (uint32_t)(wv >> 32);
                float2 f01 = __half22float2(*(__half2*)&lo32);
                float2 f23 = __half22float2(*(__half2*)&hi32);
                u64 wd0 = pack2(f01.x, f01.x);
                u64 wd1 = pack2(f01.y, f01.y);
                u64 wd2 = pack2(f23.x, f23.x);
                u64 wd3 = pack2(f23.y, f23.y);
#pragma unroll
                for (int rp = 0; rp < 4; rp++) {
                    u64 h2 = *(const u64*)&hs[k*8 + rp*2];
                    fma2(acc2[rp][0], h2, wd0);
                    fma2(acc2[rp][1], h2, wd1);
                    fma2(acc2[rp][2], h2, wd2);
                    fma2(acc2[rp][3], h2, wd3);
                }
            }
            if (!last) {
                __half* dst = &wsh[(cur ^ 1) * 8192];
#pragma unroll
                for (int i = 0; i < 4; i++) {
                    *(uint4*)&dst[(tid + 256*i)*8] = pf[i];
                }
            }
            __syncthreads();
        }
#pragma unroll
        for (int rp = 0; rp < 4; rp++) {
            float p0[2];
            float p1[2];
            float p2[2];
            float p3[2];
            unpack2(p0[0], p0[1], acc2[rp][0]);
            unpack2(p1[0], p1[1], acc2[rp][1]);
            unpack2(p2[0], p2[1], acc2[rp][2]);
            unpack2(p3[0], p3[1], acc2[rp][3]);
#pragma unroll
            for (int hh = 0; hh < 2; hh++) {
                int r = rp*2 + hh;
                float iv = sigmoidf(p0[hh]);
                float fv = sigmoidf(p1[hh]);
                float gv = tanhf(p2[hh]);
                float ov = sigmoidf(p3[hh]);
                c[r] = fv * c[r] + iv * gv;
                float hv = ov * tanhf(c[r]);
                hs[tid*8 + r] = hv;
                size_t mrow = (size_t)(n0 + r) * T + tt;
                out[mrow * ostride + dir*256 + tid] = hv;
                zh[mrow * ZKP + dir*256 + tid] = __float2half(hv);
            }
        }
        __syncthreads();
    }
}

// ---------------- sentence BiLSTM scan (1 row/block, fp16 Whh, fused gpre) -----
__global__ __launch_bounds__(256, 1)
void lstm_scan_s(const float* __restrict__ gpre,
                 const __half* __restrict__ Wt_f,
                 const __half* __restrict__ Wt_b,
                 float* __restrict__ out,
                 __half* __restrict__ zh,
                 float* __restrict__ hT,
                 int N, int T, int ostride)
{
    extern __shared__ float dynsm[];
    __half* wsh = (__half*)dynsm;
    float* hs = dynsm + 8192;
    const int tid = threadIdx.x;
    const int dir = blockIdx.x / N;
    const int n0  = blockIdx.x % N;
    const __half* __restrict__ Wt = dir ? Wt_b : Wt_f;
    const int goff = dir * Gn;

    float c0 = 0.f;
    hs[tid] = 0.f;

#pragma unroll
    for (int i = 0; i < 4; i++) {
        *(uint4*)&wsh[(tid + 256*i)*8] = *(const uint4*)&Wt[(tid + 256*i)*8];
    }
    __syncthreads();

    const int NT = 32;
    for (int step = 0; step < T; step++) {
        const int tt = dir ? (T - 1 - step) : step;
        float acc[4];
        size_t b0 = ((size_t)n0 * T + tt) * G2 + goff;
#pragma unroll
        for (int g = 0; g < 4; g++) {
            acc[g] = gpre[b0 + g*256 + tid];
        }
        for (int kt = 0; kt < NT; kt++) {
            const int cur = kt & 1;
            const bool last = (step == T-1) && (kt == NT-1);
            uint4 pf[4];
            if (!last) {
                const __half* src = &Wt[(size_t)((kt + 1) & 31) * 8192];
#pragma unroll
                for (int i = 0; i < 4; i++) {
                    pf[i] = *(const uint4*)&src[(tid + 256*i)*8];
                }
            }
#pragma unroll
            for (int kk = 0; kk < 8; kk++) {
                const int k = kt*8 + kk;
                const __half* wrow = &wsh[(cur*8 + kk)*1024];
                u64 wv = *(const u64*)(wrow + tid*4);
                uint32_t lo32 = (uint32_t)wv;
                uint32_t hi32 = (uint32_t)(wv >> 32);
                float2 f01 = __half22float2(*(__half2*)&lo32);
                float2 f23 = __half22float2(*(__half2*)&hi32);
                float hv = hs[k];
                acc[0] += hv * f01.x;
                acc[1] += hv * f01.y;
                acc[2] += hv * f23.x;
                acc[3] += hv * f23.y;
            }
            if (!last) {
                __half* dst = &wsh[(cur ^ 1) * 8192];
#pragma unroll
                for (int i = 0; i < 4; i++) {
                    *(uint4*)&dst[(tid + 256*i)*8] = pf[i];
                }
            }
            __syncthreads();
        }
        float iv = sigmoidf(acc[0]);
        float fv = sigmoidf(acc[1]);
        float gv = tanhf(acc[2]);
        float ov = sigmoidf(acc[3]);
        c0 = fv * c0 + iv * gv;
        float hv = ov * tanhf(c0);
        hs[tid] = hv;
        size_t mrow = (size_t)n0 * T + tt;
        out[mrow * ostride + dir*256 + tid] = hv;
        zh[mrow * ZKP + dir*256 + tid] = __float2half(hv);
        if (step == T - 1) {
            hT[((size_t)dir * N + n0) * 256 + tid] = hv;
        }
        __syncthreads();
    }
}

// ---------------- attention glue -----------------------------------------------
__global__ void sum_scores(const float* __restrict__ scp, float* __restrict__ sc,
                           int M, int NB)
{
    int m = blockIdx.x * blockDim.x + threadIdx.x;
    if (m >= M) return;
    float s = 0.f;
    for (int j = 0; j < NB; j++) s += scp[(size_t)m * NB + j];
    sc[m] = s;
}

__global__ void softmax_pool_kernel(const float* __restrict__ sc,
                                    const float* __restrict__ hsrc,
                                    float* __restrict__ outv,
                                    int T, int stride)
{
    __shared__ float a[64];
    __shared__ float inv_s;
    int n = blockIdx.x;
    int tid = threadIdx.x;
    if (tid == 0) {
        float mx = -1e30f;
        for (int t = 0; t < T; t++) mx = fmaxf(mx, sc[n * T + t]);
        float sum = 0.f;
        for (int t = 0; t < T; t++) {
            float e = expf(sc[n * T + t] - mx);
            a[t] = e;
            sum += e;
        }
        inv_s = 1.f / sum;
    }
    __syncthreads();
    float inv = inv_s;
    for (int col = tid; col < 2*Hn; col += blockDim.x) {
        float acc = 0.f;
        for (int t = 0; t < T; t++) {
            acc += a[t] * hsrc[((size_t)n * T + t) * stride + col];
        }
        outv[(size_t)n * (2*Hn) + col] = acc * inv;
    }
}

__global__ void build_sx_kernel(const int* __restrict__ seg,
                                const float* __restrict__ spe)
{
    int idx = blockIdx.x * blockDim.x + threadIdx.x;
    if (idx >= N1 * ZKP) return;
    int d = idx % ZKP;
    int m = idx / ZKP;
    float v;
    if (d < 2*Hn)      v = d_senvec[(size_t)m * (2*Hn) + d];
    else if (d < DATT) v = spe[(size_t)seg[m] * Pn + (d - 2*Hn)];
    else               v = 0.f;
    g_sx[idx] = __float2half(v);
}

__global__ void fill_z2pos(const int* __restrict__ seg, const float* __restrict__ spe)
{
    int idx = blockIdx.x * blockDim.x + threadIdx.x;
    if (idx >= N1 * (ZKP - 2*Hn)) return;
    int m = idx / (ZKP - 2*Hn);
    int d = idx % (ZKP - 2*Hn);
    float v = (d < Pn) ? spe[(size_t)seg[m] * Pn + d] : 0.f;
    g_z2b[(size_t)m * ZKP + 2*Hn + d] = __float2half(v);
}

// ---------------- classifier head ------------------------------------------------
__global__ void final_dense_kernel(const float* __restrict__ dW,
                                   const float* __restrict__ db,
                                   float* __restrict__ outp)
{
    __shared__ float r0[128];
    __shared__ float r1[128];
    __shared__ float r2[128];
    int b = blockIdx.x;
    int tid = threadIdx.x;
    float a0 = 0.f, a1 = 0.f, a2 = 0.f;
    for (int k = tid; k < 4*Hn; k += 128) {
        float f;
        if (k < 2*Hn)      f = d_docvec[b * 2*Hn + k];
        else if (k < 3*Hn) f = d_hT[(0 * Bn + b) * Hn + (k - 2*Hn)];
        else               f = d_hT[(1 * Bn + b) * Hn + (k - 3*Hn)];
        a0 += f * dW[0*4*Hn + k];
        a1 += f * dW[1*4*Hn + k];
        a2 += f * dW[2*4*Hn + k];
    }
    r0[tid] = a0;
    r1[tid] = a1;
    r2[tid] = a2;
    __syncthreads();
    for (int s = 64; s > 0; s >>= 1) {
        if (tid < s) {
            r0[tid] += r0[tid+s];
            r1[tid] += r1[tid+s];
            r2[tid] += r2[tid+s];
        }
        __syncthreads();
    }
    if (tid == 0) {
        outp[b*3+0] = r0[0] + db[0];
        outp[b*3+1] = r1[0] + db[1];
        outp[b*3+2] = r2[0] + db[2];
    }
}

// ---------------- host driver ------------------------------------------------------
extern "C" void kernel_launch(void* const* d_in, const int* in_sizes, int n_in,
                              void* d_out, int out_size)
{
    const int*   tok     = (const int*)d_in[0];
    const int*   wpos    = (const int*)d_in[1];
    const int*   seg     = (const int*)d_in[2];
    const float* emb     = (const float*)d_in[3];
    const float* wpe     = (const float*)d_in[4];
    const float* spe     = (const float*)d_in[5];
    const float* wWih_f  = (const float*)d_in[6];
    const float* wWhh_f  = (const float*)d_in[7];
    const float* wb_f    = (const float*)d_in[8];
    const float* wWih_b  = (const float*)d_in[9];
    const float* wWhh_b  = (const float*)d_in[10];
    const float* wb_b    = (const float*)d_in[11];
    const float* sWih_f  = (const float*)d_in[12];
    const float* sWhh_f  = (const float*)d_in[13];
    const float* sb_f    = (const float*)d_in[14];
    const float* sWih_b  = (const float*)d_in[15];
    const float* sWhh_b  = (const float*)d_in[16];
    const float* sb_b    = (const float*)d_in[17];
    const float* word_W  = (const float*)d_in[18];
    const float* word_b  = (const float*)d_in[19];
    const float* word_p  = (const float*)d_in[20];
    const float* sent_W  = (const float*)d_in[21];
    const float* sent_b  = (const float*)d_in[22];
    const float* sent_p  = (const float*)d_in[23];
    const float* dense_W = (const float*)d_in[24];
    const float* dense_b = (const float*)d_in[25];
    float* outp = (float*)d_out;

    float *pgpre, *pz, *pscp, *psc, *psenvec, *pgpre2, *pz2,
          *phT, *pscp2, *psc2, *pdocvec, *pbrep;
    __half *pwtf, *pwtb, *pstf, *pstb;
    __half *px, *pzb, *psx, *pz2b, *pwih, *psih, *pwWt, *psWt;
    cudaGetSymbolAddress((void**)&pgpre,   d_gpre);
    cudaGetSymbolAddress((void**)&pz,      d_z);
    cudaGetSymbolAddress((void**)&pscp,    d_scp);
    cudaGetSymbolAddress((void**)&psc,     d_scores);
    cudaGetSymbolAddress((void**)&psenvec, d_senvec);
    cudaGetSymbolAddress((void**)&pgpre2,  d_gpre2);
    cudaGetSymbolAddress((void**)&pz2,     d_z2);
    cudaGetSymbolAddress((void**)&phT,     d_hT);
    cudaGetSymbolAddress((void**)&pscp2,   d_scp2);
    cudaGetSymbolAddress((void**)&psc2,    d_scores2);
    cudaGetSymbolAddress((void**)&pdocvec, d_docvec);
    cudaGetSymbolAddress((void**)&pbrep,   d_brep);
    cudaGetSymbolAddress((void**)&pwtf,    g_wtf);
    cudaGetSymbolAddress((void**)&pwtb,    g_wtb);
    cudaGetSymbolAddress((void**)&pstf,    g_stf);
    cudaGetSymbolAddress((void**)&pstb,    g_stb);
    cudaGetSymbolAddress((void**)&px,      g_x);
    cudaGetSymbolAddress((void**)&pzb,     g_zb);
    cudaGetSymbolAddress((void**)&psx,     g_sx);
    cudaGetSymbolAddress((void**)&pz2b,    g_z2b);
    cudaGetSymbolAddress((void**)&pwih,    g_wih);
    cudaGetSymbolAddress((void**)&psih,    g_sih);
    cudaGetSymbolAddress((void**)&pwWt,    g_wWt);
    cudaGetSymbolAddress((void**)&psWt,    g_sWt);

    cudaFuncSetAttribute(lstm_scan_w, cudaFuncAttributeMaxDynamicSharedMemorySize,
                         32768 + 256*8*4);
    cudaFuncSetAttribute(lstm_scan_s, cudaFuncAttributeMaxDynamicSharedMemorySize,
                         32768 + 256*4);
    cudaFuncSetAttribute(gemm_h, cudaFuncAttributeMaxDynamicSharedMemorySize,
                         GEMM_SMEM2);

    // 1. gather + padding
    gather_x_kernel<<<(M1*DIN1 + 255)/256, 256>>>(tok, wpos, emb, wpe);
    pad_x_kernel<<<(M1*(XKP-DIN1) + 255)/256, 256>>>();
    pad_z_kernel<<<(M1*(ZKP-DATT) + 255)/256, 256>>>();

    // 2. weight conversions (concat fwd|bwd Wih)
    conv_pad<<<(Gn*XKP + 255)/256, 256>>>(wWih_f, pwih,             Gn, DIN1, XKP);
    conv_pad<<<(Gn*XKP + 255)/256, 256>>>(wWih_b, pwih + Gn*XKP,    Gn, DIN1, XKP);
    conv_pad<<<(Gn*ZKP + 255)/256, 256>>>(sWih_f, psih,             Gn, DATT, ZKP);
    conv_pad<<<(Gn*ZKP + 255)/256, 256>>>(sWih_b, psih + Gn*ZKP,    Gn, DATT, ZKP);
    conv_wt<<<(ZKP*ZKP + 255)/256, 256>>>(word_W, pwWt, DATT, ZKP, ZKP);
    conv_wt<<<(ZKP*ZKP + 255)/256, 256>>>(sent_W, psWt, DATT, ZKP, ZKP);
    conv_whh<<<(Hn*Gn + 255)/256, 256>>>(wWhh_f, pwtf);
    conv_whh<<<(Hn*Gn + 255)/256, 256>>>(wWhh_b, pwtb);
    conv_whh<<<(Hn*Gn + 255)/256, 256>>>(sWhh_f, pstf);
    conv_whh<<<(Hn*Gn + 255)/256, 256>>>(sWhh_b, pstb);

    // 3. fused word input GEMM (fwd|bwd in one launch, N=2048)
    rep_bias2<<<(16*G2 + 255)/256, 256>>>(wb_f, wb_b);
    {
        dim3 g(G2/128, M1/128);
        gemm_h<<<g, 256, GEMM_SMEM2>>>(px, pwih, pbrep, (const float*)0,
                                       (const float*)0, pgpre, M1, G2, XKP, G2, 0);
    }

    // 4. word BiLSTM scan -> d_z fp32 + z fp16
    lstm_scan_w<<<128, 256, 32768 + 256*8*4>>>(pgpre, pwtf, pwtb, pz,
                                               pzb, N1, Ln, DATT);

    // 5. word attention
    gemm_h<<<dim3(NBATT, M1/128), 256, GEMM_SMEM2>>>(pzb, pwWt, (const float*)0,
                                                     word_b, word_p,
                                                     pscp, M1, ZKP, ZKP, DATT, 1);
    sum_scores<<<(M1 + 255)/256, 256>>>(pscp, psc, M1, NBATT);
    softmax_pool_kernel<<<N1, 256>>>(psc, pz, psenvec, Ln, DATT);

    // 6. sentence input (fused fwd|bwd GEMM)
    build_sx_kernel<<<(N1*ZKP + 255)/256, 256>>>(seg, spe);
    fill_z2pos<<<(N1*(ZKP-2*Hn) + 255)/256, 256>>>(seg, spe);
    rep_bias2<<<(16*G2 + 255)/256, 256>>>(sb_f, sb_b);
    {
        dim3 g(G2/128, N1/128);
        gemm_h<<<g, 256, GEMM_SMEM2>>>(psx, psih, pbrep, (const float*)0,
                                       (const float*)0, pgpre2, N1, G2, ZKP, G2, 0);
    }

    // 7. sentence BiLSTM scan -> d_z2 fp32 + z2 fp16, keeps hT
    lstm_scan_s<<<2*Bn, 256, 32768 + 256*4>>>(pgpre2, pstf, pstb, pz2,
                                              pz2b, phT, Bn, Sn, DATT);

    // 8. sentence attention
    gemm_h<<<dim3(NBATT, N1/128), 256, GEMM_SMEM2>>>(pz2b, psWt, (const float*)0,
                                                     sent_b, sent_p,
                                                     pscp2, N1, ZKP, ZKP, DATT, 1);
    sum_scores<<<(N1 + 255)/256, 256>>>(pscp2, psc2, N1, NBATT);
    softmax_pool_kernel<<<Bn, 256>>>(psc2, pz2, pdocvec, Sn, DATT);

    // 9. classifier head
    final_dense_kernel<<<Bn, 128>>>(dense_W, dense_b, outp);
}